// round 14
// baseline (speedup 1.0000x reference)
#include <cuda_runtime.h>
#include <cuda_bf16.h>
#include <math.h>

// ---------------- problem constants ----------------
#define BATCH 4
#define CIN   64
#define HH    256
#define WW    256
#define MID   128
#define P     1024
#define LSEQ  128
#define NST   16
#define KDIM  96
#define NBLK  128
#define NBLK_B 32

// ---------------- device scratch ----------------
__device__ float  g_h[BATCH*MID*P];
__device__ float  g_u[BATCH*MID*P];
__device__ float  g_res[BATCH*MID*P];
__device__ __align__(16) float g_xdbl[BATCH*LSEQ*KDIM];
__device__ float2 g_gnp0[BATCH*2*16];
__device__ float2 g_gnp1[BATCH*2*32];
__device__ unsigned g_jobc[BATCH];          // upsample work-stealing counters

// per-batch grid barrier state (generation-based; monotonic across graph replays)
__device__ volatile unsigned g_gen[BATCH];
__device__ unsigned g_cnt[BATCH];

__device__ __forceinline__ void grid_bar_b(int b){
    __syncthreads();
    if (threadIdx.x == 0){
        __threadfence();
        unsigned old = g_gen[b];
        unsigned rank = atomicAdd(&g_cnt[b], 1u);
        if (rank == NBLK_B - 1){
            g_cnt[b] = 0;
            __threadfence();
            atomicAdd((unsigned*)&g_gen[b], 1u);
        } else {
            while (g_gen[b] == old) { __nanosleep(32); }
        }
        __threadfence();
    }
    __syncthreads();
}

__device__ __forceinline__ float silu_f(float v){ return v / (1.f + __expf(-v)); }

#define SCAN_SMEM_FLOATS 23360
#define SCAN_SMEM_BYTES  (SCAN_SMEM_FLOATS*4)

// =========================== MEGA KERNEL ===========================
__global__ void __launch_bounds__(1024, 1)
k_mega(const float* __restrict__ x, const float* __restrict__ w_in, const float* __restrict__ b_in,
       const float* __restrict__ gn0g, const float* __restrict__ gn0b, const float* __restrict__ ip0w,
       const float* __restrict__ c0w,  const float* __restrict__ c0b,  const float* __restrict__ xp0,
       const float* __restrict__ dt0w, const float* __restrict__ dt0b, const float* __restrict__ al0,
       const float* __restrict__ dd0,
       const float* __restrict__ gn1g, const float* __restrict__ gn1b, const float* __restrict__ ip1w,
       const float* __restrict__ c1w,  const float* __restrict__ c1b,  const float* __restrict__ xp1,
       const float* __restrict__ dt1w, const float* __restrict__ dt1b, const float* __restrict__ al1,
       const float* __restrict__ dd1,
       const float* __restrict__ wout, const float* __restrict__ bout, float* __restrict__ out)
{
    extern __shared__ float sm[];   // scan workspace (93 KB)
    __shared__ __align__(16) float4 sP[34*34];
    __shared__ __align__(16) float  sU[4][P];
    __shared__ __align__(16) float4 sW4[9][4];
    __shared__ float sMI[4];
    __shared__ float swdc[4][2][8][8];
    __shared__ float red[64];
    __shared__ __align__(16) float sCo[1024];
    __shared__ unsigned sJob;

    int bid = blockIdx.x;
    int b = bid >> 5, q = bid & 31;     // q = group/dtile index
    int tid = threadIdx.x;

    // ================= phase 0: downconv (8x8 stride 8) + GN0 stats =================
    {
        int g = q;
        if (g == 0 && tid == 0) g_jobc[b] = 0;   // reset upsample job queue for this launch
        int ty = tid >> 5, tx = tid & 31;
        if (tid < 512){
            int oc4 = tid >> 7, rem = tid & 127;
            swdc[oc4][rem>>6][(rem>>3)&7][rem&7] = w_in[(4*g + oc4)*128 + rem];
        }
        __syncthreads();
        float acc0=0.f, acc1=0.f, acc2=0.f, acc3=0.f;
        #pragma unroll
        for (int ic = 0; ic < 2; ic++){
            const float* xb = x + (((size_t)b*CIN + 2*g + ic)*HH + ty*8)*WW + tx*8;
            #pragma unroll
            for (int ky = 0; ky < 8; ky++){
                const float4* r = (const float4*)(xb + ky*WW);
                float4 v0 = r[0], v1 = r[1];
                float xv[8] = {v0.x,v0.y,v0.z,v0.w,v1.x,v1.y,v1.z,v1.w};
                #pragma unroll
                for (int kx = 0; kx < 8; kx++){
                    float xvv = xv[kx];
                    acc0 = fmaf(xvv, swdc[0][ic][ky][kx], acc0);
                    acc1 = fmaf(xvv, swdc[1][ic][ky][kx], acc1);
                    acc2 = fmaf(xvv, swdc[2][ic][ky][kx], acc2);
                    acc3 = fmaf(xvv, swdc[3][ic][ky][kx], acc3);
                }
            }
        }
        acc0 += b_in[4*g+0]; acc1 += b_in[4*g+1]; acc2 += b_in[4*g+2]; acc3 += b_in[4*g+3];
        int p = ty*32 + tx;
        g_h[(b*MID + 4*g + 0)*P + p] = acc0;
        g_h[(b*MID + 4*g + 1)*P + p] = acc1;
        g_h[(b*MID + 4*g + 2)*P + p] = acc2;
        g_h[(b*MID + 4*g + 3)*P + p] = acc3;
        float s  = acc0 + acc1 + acc2 + acc3;
        float s2 = acc0*acc0 + acc1*acc1 + acc2*acc2 + acc3*acc3;
        #pragma unroll
        for (int o = 16; o; o >>= 1){
            s  += __shfl_xor_sync(0xffffffffu, s,  o);
            s2 += __shfl_xor_sync(0xffffffffu, s2, o);
        }
        int wid = tid >> 5, lid = tid & 31;
        if (lid == 0){ red[wid] = s; red[32+wid] = s2; }
        __syncthreads();
        if (tid < 32){
            s = red[tid]; s2 = red[32+tid];
            #pragma unroll
            for (int o = 16; o; o >>= 1){
                s  += __shfl_xor_sync(0xffffffffu, s,  o);
                s2 += __shfl_xor_sync(0xffffffffu, s2, o);
            }
            if (tid == 0){
                int grp = g >> 4;
                g_gnp0[(b*2 + grp)*16 + (g & 15)] = make_float2(s, s2);
            }
        }
    }
    grid_bar_b(b);

    // ================= mamba blocks =================
    #pragma unroll 1
    for (int blk = 0; blk < 2; blk++){
        const float* w     = blk ? ip1w : ip0w;
        const float* cw    = blk ? c1w  : c0w;
        const float* cb    = blk ? c1b  : c0b;
        const float* gamma = blk ? gn1g : gn0g;
        const float* beta  = blk ? gn1b : gn0b;
        const float* xproj = blk ? xp1  : xp0;
        const float* dtw   = blk ? dt1w : dt0w;
        const float* dtb   = blk ? dt1b : dt0b;
        const float* alog  = blk ? al1  : al0;
        const float* dd    = blk ? dd1  : dd0;

        // ---------- inproj: GN + 3x3 conv + conv0+SiLU + gate + x_dbl ----------
        {
            int g = q;
            int p = tid;
            int wq = p >> 5, lane = p & 31;
            int cx0 = 2*g, cx1 = 2*g+1, cg0 = 64+2*g, cg1 = 65+2*g;
            float hv0 = g_h[(b*MID + cx0)*P + p];
            float hv1 = g_h[(b*MID + cx1)*P + p];
            float hv2 = g_h[(b*MID + cg0)*P + p];
            float hv3 = g_h[(b*MID + cg1)*P + p];
            if (wq < 2){
                int npart = blk ? 32 : 16;
                float2 v = make_float2(0.f, 0.f);
                if (lane < npart) v = blk ? g_gnp1[(b*2+wq)*32 + lane] : g_gnp0[(b*2+wq)*16 + lane];
                float s = v.x, s2v = v.y;
                #pragma unroll
                for (int o = 16; o; o >>= 1){
                    s   += __shfl_xor_sync(0xffffffffu, s,   o);
                    s2v += __shfl_xor_sync(0xffffffffu, s2v, o);
                }
                if (lane == 0){
                    float mean = s * (1.f/65536.f);
                    float var  = s2v * (1.f/65536.f) - mean*mean;
                    sMI[wq*2]   = mean;
                    sMI[wq*2+1] = rsqrtf(var + 1e-5f);
                }
            }
            if (p >= 64 && p < 100){
                int idx = p - 64;
                int t = idx / 4, j = idx & 3;
                float4 wv;
                wv.x = w[(4*g + j)*18 +     t];
                wv.y = w[(4*g + j)*18 + 9 + t];
                wv.z = w[(128 + 4*g + j)*18 +     t];
                wv.w = w[(128 + 4*g + j)*18 + 9 + t];
                sW4[t][j] = wv;
            }
            if (p >= 128 && p < 260){
                int i = p - 128;
                int cell;
                if (i < 34)       cell = i;
                else if (i < 68)  cell = 33*34 + (i - 34);
                else if (i < 100) cell = (i - 68 + 1)*34;
                else              cell = (i - 100 + 1)*34 + 33;
                sP[cell] = make_float4(0.f, 0.f, 0.f, 0.f);
            }
            __syncthreads();
            int y = p >> 5, xx0 = p & 31;
            {
                float m0 = sMI[0], i0 = sMI[1], m1 = sMI[2], i1 = sMI[3];
                float ga0 = gamma[cx0]*i0, be0 = beta[cx0] - m0*ga0;
                float ga1 = gamma[cx1]*i0, be1 = beta[cx1] - m0*ga1;
                float ga2 = gamma[cg0]*i1, be2 = beta[cg0] - m1*ga2;
                float ga3 = gamma[cg1]*i1, be3 = beta[cg1] - m1*ga3;
                float4 v;
                v.x = hv0*ga0 + be0;
                v.y = hv1*ga1 + be1;
                v.z = hv2*ga2 + be2;
                v.w = hv3*ga3 + be3;
                sP[(y+1)*34 + (xx0+1)] = v;
            }
            __syncthreads();
            float accx[4] = {0.f,0.f,0.f,0.f};
            float accg[4] = {0.f,0.f,0.f,0.f};
            #pragma unroll
            for (int ky = 0; ky < 3; ky++){
                #pragma unroll
                for (int kx = 0; kx < 3; kx++){
                    float4 v = sP[(y+ky)*34 + (xx0+kx)];
                    int t = ky*3 + kx;
                    #pragma unroll
                    for (int j = 0; j < 4; j++){
                        float4 W = sW4[t][j];
                        accx[j] = fmaf(v.x, W.x, fmaf(v.y, W.y, accx[j]));
                        accg[j] = fmaf(v.z, W.z, fmaf(v.w, W.w, accg[j]));
                    }
                }
            }
            #pragma unroll
            for (int j = 0; j < 4; j++){
                int c = 4*g + j;
                g_res[(b*MID + c)*P + p] = silu_f(accg[j]);
            }
            #pragma unroll
            for (int j = 0; j < 4; j++){
                int c = 4*g + j;
                float lo = (j < 2) ? accx[0] : accx[2];
                float hi = (j < 2) ? accx[1] : accx[3];
                float v = fmaf(lo, cw[c*2], fmaf(hi, cw[c*2+1], cb[c]));
                float uv = silu_f(v);
                g_u[(b*MID + c)*P + p] = uv;
                sU[j][p] = uv;
            }
            __syncthreads();
            const float4* xpr0 = (const float4*)(xproj + (wq*3 + 0)*P);
            const float4* xpr1 = (const float4*)(xproj + (wq*3 + 1)*P);
            const float4* xpr2 = (const float4*)(xproj + (wq*3 + 2)*P);
            const float4* u0p = (const float4*)sU[0];
            const float4* u1p = (const float4*)sU[1];
            const float4* u2p = (const float4*)sU[2];
            const float4* u3p = (const float4*)sU[3];
            float a00=0,a01=0,a02=0, a10=0,a11=0,a12=0, a20=0,a21=0,a22=0, a30=0,a31=0,a32=0;
            float4 w0n = xpr0[lane], w1n = xpr1[lane], w2n = xpr2[lane];
            #pragma unroll
            for (int i = 0; i < 8; i++){
                int px = i*32 + lane;
                float4 w0 = w0n, w1 = w1n, w2 = w2n;
                if (i < 7){
                    int pxn = px + 32;
                    w0n = xpr0[pxn]; w1n = xpr1[pxn]; w2n = xpr2[pxn];
                }
                float4 u0 = u0p[px], u1 = u1p[px], u2 = u2p[px], u3 = u3p[px];
                a00 = fmaf(u0.x,w0.x,a00); a00 = fmaf(u0.y,w0.y,a00); a00 = fmaf(u0.z,w0.z,a00); a00 = fmaf(u0.w,w0.w,a00);
                a01 = fmaf(u0.x,w1.x,a01); a01 = fmaf(u0.y,w1.y,a01); a01 = fmaf(u0.z,w1.z,a01); a01 = fmaf(u0.w,w1.w,a01);
                a02 = fmaf(u0.x,w2.x,a02); a02 = fmaf(u0.y,w2.y,a02); a02 = fmaf(u0.z,w2.z,a02); a02 = fmaf(u0.w,w2.w,a02);
                a10 = fmaf(u1.x,w0.x,a10); a10 = fmaf(u1.y,w0.y,a10); a10 = fmaf(u1.z,w0.z,a10); a10 = fmaf(u1.w,w0.w,a10);
                a11 = fmaf(u1.x,w1.x,a11); a11 = fmaf(u1.y,w1.y,a11); a11 = fmaf(u1.z,w1.z,a11); a11 = fmaf(u1.w,w1.w,a11);
                a12 = fmaf(u1.x,w2.x,a12); a12 = fmaf(u1.y,w2.y,a12); a12 = fmaf(u1.z,w2.z,a12); a12 = fmaf(u1.w,w2.w,a12);
                a20 = fmaf(u2.x,w0.x,a20); a20 = fmaf(u2.y,w0.y,a20); a20 = fmaf(u2.z,w0.z,a20); a20 = fmaf(u2.w,w0.w,a20);
                a21 = fmaf(u2.x,w1.x,a21); a21 = fmaf(u2.y,w1.y,a21); a21 = fmaf(u2.z,w1.z,a21); a21 = fmaf(u2.w,w1.w,a21);
                a22 = fmaf(u2.x,w2.x,a22); a22 = fmaf(u2.y,w2.y,a22); a22 = fmaf(u2.z,w2.z,a22); a22 = fmaf(u2.w,w2.w,a22);
                a30 = fmaf(u3.x,w0.x,a30); a30 = fmaf(u3.y,w0.y,a30); a30 = fmaf(u3.z,w0.z,a30); a30 = fmaf(u3.w,w0.w,a30);
                a31 = fmaf(u3.x,w1.x,a31); a31 = fmaf(u3.y,w1.y,a31); a31 = fmaf(u3.z,w1.z,a31); a31 = fmaf(u3.w,w1.w,a31);
                a32 = fmaf(u3.x,w2.x,a32); a32 = fmaf(u3.y,w2.y,a32); a32 = fmaf(u3.z,w2.z,a32); a32 = fmaf(u3.w,w2.w,a32);
            }
            #pragma unroll
            for (int o = 16; o; o >>= 1){
                a00 += __shfl_xor_sync(0xffffffffu, a00, o); a01 += __shfl_xor_sync(0xffffffffu, a01, o);
                a02 += __shfl_xor_sync(0xffffffffu, a02, o); a10 += __shfl_xor_sync(0xffffffffu, a10, o);
                a11 += __shfl_xor_sync(0xffffffffu, a11, o); a12 += __shfl_xor_sync(0xffffffffu, a12, o);
                a20 += __shfl_xor_sync(0xffffffffu, a20, o); a21 += __shfl_xor_sync(0xffffffffu, a21, o);
                a22 += __shfl_xor_sync(0xffffffffu, a22, o); a30 += __shfl_xor_sync(0xffffffffu, a30, o);
                a31 += __shfl_xor_sync(0xffffffffu, a31, o); a32 += __shfl_xor_sync(0xffffffffu, a32, o);
            }
            if (lane == 0){
                int k = wq*3;
                float* r0 = g_xdbl + (b*LSEQ + 4*g + 0)*KDIM + k;
                float* r1 = g_xdbl + (b*LSEQ + 4*g + 1)*KDIM + k;
                float* r2 = g_xdbl + (b*LSEQ + 4*g + 2)*KDIM + k;
                float* r3 = g_xdbl + (b*LSEQ + 4*g + 3)*KDIM + k;
                r0[0]=a00; r0[1]=a01; r0[2]=a02;
                r1[0]=a10; r1[1]=a11; r1[2]=a12;
                r2[0]=a20; r2[1]=a21; r2[2]=a22;
                r3[0]=a30; r3[1]=a31; r3[2]=a32;
            }
        }
        grid_bar_b(b);

        // ---------- scan: delta GEMM + softplus + selective scan + combine + GN1 ----------
        {
            int dt = q;
            float*  sXd = sm;                    // [128][68]; later sY overlay
            float*  sWs = sm + 8704;             // [64][33]; later GN scratch
            float*  sB  = sm + 10816;            // [128][16]
            float*  sC  = sm + 12864;            // [128][16]
            float*  sDelta = sm + 14912;         // [128][33]
            float*  sUt    = sm + 19136;         // [128][33]
            float*  sY     = sm;                 // overlay

            for (int idx = tid; idx < 128*64; idx += 1024){
                int l = idx >> 6, k = idx & 63;
                sXd[l*68 + k] = g_xdbl[(b*LSEQ + l)*KDIM + k];
            }
            for (int idx = tid; idx < 128*16; idx += 1024){
                int l = idx >> 4, n = idx & 15;
                const float* row = g_xdbl + (b*LSEQ + l)*KDIM;
                sB[l*16 + n] = row[64 + n];
                sC[l*16 + n] = row[80 + n];
            }
            for (int idx = tid; idx < 32*64; idx += 1024){
                int dl = idx >> 6, r = idx & 63;
                sWs[r*33 + dl] = dtw[(dt*32 + dl)*64 + r];
            }
            for (int idx = tid; idx < 128*32; idx += 1024){
                int l = idx >> 5, dj = idx & 31;
                sUt[l*33 + dj] = g_u[(b*LSEQ + l)*P + dt*32 + dj];
            }
            __syncthreads();

            // delta GEMM: thread = (4 l's) x (dloc)
            {
                int dloc = tid & 31, lbase = (tid >> 5) << 2;
                float acc[4] = {0.f,0.f,0.f,0.f};
                #pragma unroll
                for (int k0 = 0; k0 < 64; k0 += 16){
                    float wv[16];
                    #pragma unroll
                    for (int j = 0; j < 16; j++) wv[j] = sWs[(k0+j)*33 + dloc];
                    #pragma unroll
                    for (int l = 0; l < 4; l++){
                        const float4* row = (const float4*)(sXd + (lbase+l)*68 + k0);
                        float4 x0 = row[0], x1 = row[1], x2 = row[2], x3 = row[3];
                        float a = acc[l];
                        a = fmaf(x0.x,wv[0],a);  a = fmaf(x0.y,wv[1],a);  a = fmaf(x0.z,wv[2],a);  a = fmaf(x0.w,wv[3],a);
                        a = fmaf(x1.x,wv[4],a);  a = fmaf(x1.y,wv[5],a);  a = fmaf(x1.z,wv[6],a);  a = fmaf(x1.w,wv[7],a);
                        a = fmaf(x2.x,wv[8],a);  a = fmaf(x2.y,wv[9],a);  a = fmaf(x2.z,wv[10],a); a = fmaf(x2.w,wv[11],a);
                        a = fmaf(x3.x,wv[12],a); a = fmaf(x3.y,wv[13],a); a = fmaf(x3.z,wv[14],a); a = fmaf(x3.w,wv[15],a);
                        acc[l] = a;
                    }
                }
                float bias = dtb[dt*32 + dloc];
                #pragma unroll
                for (int l = 0; l < 4; l++){
                    float xv = acc[l] + bias;
                    sDelta[(lbase+l)*33 + dloc] = fmaxf(xv, 0.f) + __logf(1.f + __expf(-fabsf(xv)));
                }
            }
            __syncthreads();

            // scan: 512 threads, thread = (dl = tid>>4) x (n = tid&15)
            if (tid < 512){
                int dl = tid >> 4;
                int n  = tid & 15;
                int d = dt*32 + dl;
                float An = -expf(alog[d*16 + n]);
                float Dd = dd[d];
                float cr = 0.f;
                #pragma unroll 4
                for (int l = 0; l < LSEQ; l++){
                    float td = sDelta[l*33 + dl];
                    float tu = sUt[l*33 + dl];
                    float du = td * tu;
                    cr = fmaf(__expf(td*An), cr, du*sB[l*16 + n]);
                    float yv = cr * sC[l*16 + n];
                    yv += __shfl_xor_sync(0xffffffffu, yv, 1);
                    yv += __shfl_xor_sync(0xffffffffu, yv, 2);
                    yv += __shfl_xor_sync(0xffffffffu, yv, 4);
                    yv += __shfl_xor_sync(0xffffffffu, yv, 8);
                    if (n == 0) sY[l*33 + dl] = fmaf(tu, Dd, yv);
                }
            }
            __syncthreads();

            // combine h += y*silu(res) and GN1 partial stats
            float s0 = 0.f, q0 = 0.f, s1 = 0.f, q1 = 0.f;
            for (int e = tid; e < 128*32; e += 1024){
                int l = e >> 5, dj = e & 31;
                int idx = (b*LSEQ + l)*P + dt*32 + dj;
                float h = fmaf(sY[l*33 + dj], g_res[idx], g_h[idx]);
                g_h[idx] = h;
                if (l < 64){ s0 += h; q0 += h*h; } else { s1 += h; q1 += h*h; }
            }
            if (blk == 0){
                #pragma unroll
                for (int o = 16; o; o >>= 1){
                    s0 += __shfl_xor_sync(0xffffffffu, s0, o);
                    q0 += __shfl_xor_sync(0xffffffffu, q0, o);
                    s1 += __shfl_xor_sync(0xffffffffu, s1, o);
                    q1 += __shfl_xor_sync(0xffffffffu, q1, o);
                }
                int wid = tid >> 5;
                __syncthreads();
                if ((tid & 31) == 0){
                    sWs[wid*4+0] = s0; sWs[wid*4+1] = q0; sWs[wid*4+2] = s1; sWs[wid*4+3] = q1;
                }
                __syncthreads();
                if (tid == 0){
                    float S0=0,Q0=0,S1=0,Q1=0;
                    #pragma unroll
                    for (int i = 0; i < 32; i++){ S0+=sWs[i*4]; Q0+=sWs[i*4+1]; S1+=sWs[i*4+2]; Q1+=sWs[i*4+3]; }
                    g_gnp1[(b*2 + 0)*32 + dt] = make_float2(S0, Q0);
                    g_gnp1[(b*2 + 1)*32 + dt] = make_float2(S1, Q1);
                }
            }
        }
        grid_bar_b(b);
    }

    // ================= conv_out + x8 bilinear upsample (work-stealing planes) =================
    {
        int lane64 = tid & 63;
        int ry2 = tid >> 6;                 // 0..15
        int ii = lane64 >> 1;               // source col 0..31
        int jh = lane64 & 1;                // which half of the 8-wide output group
        int ca = jh ? ii : (ii > 0 ? ii - 1 : 0);
        int cbx = jh ? (ii < 31 ? ii + 1 : 31) : ii;
        float wxa = jh ? 0.0625f : 0.5625f;
        for (;;){
            __syncthreads();                // protects sJob & sCo reuse
            if (tid == 0) sJob = atomicAdd(&g_jobc[b], 1u);
            __syncthreads();
            unsigned j = sJob;
            if (j >= 128u) break;
            int oc = (int)j;
            int g = oc >> 2;
            const float* hb = g_h + (size_t)(b*MID + 4*g)*P;
            if (tid < 256){
                float w0 = wout[oc*4], w1 = wout[oc*4+1], w2 = wout[oc*4+2], w3 = wout[oc*4+3];
                float bias = bout[oc];
                float4 a  = ((const float4*)hb)[tid];
                float4 c1 = ((const float4*)(hb+P))[tid];
                float4 c2 = ((const float4*)(hb+2*P))[tid];
                float4 c3 = ((const float4*)(hb+3*P))[tid];
                float4 r;
                r.x = bias + a.x*w0 + c1.x*w1 + c2.x*w2 + c3.x*w3;
                r.y = bias + a.y*w0 + c1.y*w1 + c2.y*w2 + c3.y*w3;
                r.z = bias + a.z*w0 + c1.z*w1 + c2.z*w2 + c3.z*w3;
                r.w = bias + a.w*w0 + c1.w*w1 + c2.w*w2 + c3.w*w3;
                ((float4*)sCo)[tid] = r;
            }
            __syncthreads();
            float* obase = out + ((size_t)(b*MID + oc))*256*256;
            #pragma unroll 4
            for (int t = 0; t < 16; t++){
                int oy = t*16 + ry2;
                float sy = (oy + 0.5f) * 0.125f - 0.5f;
                int iy = (int)floorf(sy);
                float fy = sy - (float)iy;
                int iy0 = iy < 0 ? 0 : iy;
                int iy1 = (iy + 1 > 31) ? 31 : iy + 1;
                const float* r0 = sCo + iy0*32;
                const float* r1 = sCo + iy1*32;
                float a0 = r0[ca], a1 = r1[ca];
                float b0 = r0[cbx], b1 = r1[cbx];
                float va = a0 + (a1 - a0) * fy;
                float vb = b0 + (b1 - b0) * fy;
                float dab = vb - va;
                float4 v;
                v.x = fmaf(dab, wxa,            va);
                v.y = fmaf(dab, wxa + 0.125f,   va);
                v.z = fmaf(dab, wxa + 0.25f,    va);
                v.w = fmaf(dab, wxa + 0.375f,   va);
                ((float4*)(obase + oy*256))[lane64] = v;
            }
        }
    }
}

// ---------------- host orchestration ----------------
extern "C" void kernel_launch(void* const* d_in, const int* in_sizes, int n_in,
                              void* d_out, int out_size){
    cudaFuncSetAttribute(k_mega, cudaFuncAttributeMaxDynamicSharedMemorySize, SCAN_SMEM_BYTES);

    k_mega<<<NBLK, 1024, SCAN_SMEM_BYTES>>>(
        (const float*)d_in[0],  (const float*)d_in[1],  (const float*)d_in[2],
        (const float*)d_in[3],  (const float*)d_in[4],  (const float*)d_in[5],
        (const float*)d_in[6],  (const float*)d_in[7],  (const float*)d_in[8],
        (const float*)d_in[9],  (const float*)d_in[10], (const float*)d_in[11],
        (const float*)d_in[12],
        (const float*)d_in[13], (const float*)d_in[14], (const float*)d_in[15],
        (const float*)d_in[16], (const float*)d_in[17], (const float*)d_in[18],
        (const float*)d_in[19], (const float*)d_in[20], (const float*)d_in[21],
        (const float*)d_in[22],
        (const float*)d_in[23], (const float*)d_in[24], (float*)d_out);
}

// round 15
// speedup vs baseline: 1.0776x; 1.0776x over previous
#include <cuda_runtime.h>
#include <cuda_bf16.h>
#include <math.h>

// ---------------- problem constants ----------------
#define BATCH 4
#define CIN   64
#define HH    256
#define WW    256
#define MID   128
#define P     1024
#define LSEQ  128
#define NST   16
#define KDIM  96
#define NBLK  128
#define NBLK_B 32

// ---------------- device scratch ----------------
__device__ float  g_h[BATCH*MID*P];
__device__ float  g_u[BATCH*MID*P];
__device__ float  g_res[BATCH*MID*P];
__device__ __align__(16) float g_xdbl[BATCH*LSEQ*KDIM];
__device__ float2 g_gnp0[BATCH*2*16];
__device__ float2 g_gnp1[BATCH*2*32];

// per-batch grid barrier state (generation-based; monotonic across graph replays)
__device__ volatile unsigned g_gen[BATCH];
__device__ unsigned g_cnt[BATCH];

__device__ __forceinline__ void grid_bar_b(int b){
    __syncthreads();
    if (threadIdx.x == 0){
        __threadfence();
        unsigned old = g_gen[b];
        unsigned rank = atomicAdd(&g_cnt[b], 1u);
        if (rank == NBLK_B - 1){
            g_cnt[b] = 0;
            __threadfence();
            atomicAdd((unsigned*)&g_gen[b], 1u);
        } else {
            while (g_gen[b] == old) { __nanosleep(32); }
        }
        __threadfence();
    }
    __syncthreads();
}

__device__ __forceinline__ float silu_f(float v){ return v / (1.f + __expf(-v)); }

#define SCAN_SMEM_FLOATS 23360
#define SCAN_SMEM_BYTES  (SCAN_SMEM_FLOATS*4)

// =========================== MEGA KERNEL ===========================
__global__ void __launch_bounds__(1024, 1)
k_mega(const float* __restrict__ x, const float* __restrict__ w_in, const float* __restrict__ b_in,
       const float* __restrict__ gn0g, const float* __restrict__ gn0b, const float* __restrict__ ip0w,
       const float* __restrict__ c0w,  const float* __restrict__ c0b,  const float* __restrict__ xp0,
       const float* __restrict__ dt0w, const float* __restrict__ dt0b, const float* __restrict__ al0,
       const float* __restrict__ dd0,
       const float* __restrict__ gn1g, const float* __restrict__ gn1b, const float* __restrict__ ip1w,
       const float* __restrict__ c1w,  const float* __restrict__ c1b,  const float* __restrict__ xp1,
       const float* __restrict__ dt1w, const float* __restrict__ dt1b, const float* __restrict__ al1,
       const float* __restrict__ dd1,
       const float* __restrict__ wout, const float* __restrict__ bout, float* __restrict__ out)
{
    extern __shared__ float sm[];   // scan workspace (93 KB)
    __shared__ __align__(16) float4 sP[34*34];
    __shared__ __align__(16) float  sU[4][P];
    __shared__ __align__(16) float4 sW4[9][4];
    __shared__ float sMI[4];
    __shared__ float swdc[4][2][8][8];
    __shared__ float red[64];
    __shared__ __align__(16) float sCo[1024];

    int bid = blockIdx.x;
    int b = bid >> 5, q = bid & 31;     // q = group/dtile index
    int tid = threadIdx.x;

    // ================= phase 0: downconv (8x8 stride 8) + GN0 stats =================
    {
        int g = q;
        int ty = tid >> 5, tx = tid & 31;
        if (tid < 512){
            int oc4 = tid >> 7, rem = tid & 127;
            swdc[oc4][rem>>6][(rem>>3)&7][rem&7] = w_in[(4*g + oc4)*128 + rem];
        }
        __syncthreads();
        float acc0=0.f, acc1=0.f, acc2=0.f, acc3=0.f;
        #pragma unroll
        for (int ic = 0; ic < 2; ic++){
            const float* xb = x + (((size_t)b*CIN + 2*g + ic)*HH + ty*8)*WW + tx*8;
            #pragma unroll
            for (int ky = 0; ky < 8; ky++){
                const float4* r = (const float4*)(xb + ky*WW);
                float4 v0 = r[0], v1 = r[1];
                float xv[8] = {v0.x,v0.y,v0.z,v0.w,v1.x,v1.y,v1.z,v1.w};
                #pragma unroll
                for (int kx = 0; kx < 8; kx++){
                    float xvv = xv[kx];
                    acc0 = fmaf(xvv, swdc[0][ic][ky][kx], acc0);
                    acc1 = fmaf(xvv, swdc[1][ic][ky][kx], acc1);
                    acc2 = fmaf(xvv, swdc[2][ic][ky][kx], acc2);
                    acc3 = fmaf(xvv, swdc[3][ic][ky][kx], acc3);
                }
            }
        }
        acc0 += b_in[4*g+0]; acc1 += b_in[4*g+1]; acc2 += b_in[4*g+2]; acc3 += b_in[4*g+3];
        int p = ty*32 + tx;
        g_h[(b*MID + 4*g + 0)*P + p] = acc0;
        g_h[(b*MID + 4*g + 1)*P + p] = acc1;
        g_h[(b*MID + 4*g + 2)*P + p] = acc2;
        g_h[(b*MID + 4*g + 3)*P + p] = acc3;
        float s  = acc0 + acc1 + acc2 + acc3;
        float s2 = acc0*acc0 + acc1*acc1 + acc2*acc2 + acc3*acc3;
        #pragma unroll
        for (int o = 16; o; o >>= 1){
            s  += __shfl_xor_sync(0xffffffffu, s,  o);
            s2 += __shfl_xor_sync(0xffffffffu, s2, o);
        }
        int wid = tid >> 5, lid = tid & 31;
        if (lid == 0){ red[wid] = s; red[32+wid] = s2; }
        __syncthreads();
        if (tid < 32){
            s = red[tid]; s2 = red[32+tid];
            #pragma unroll
            for (int o = 16; o; o >>= 1){
                s  += __shfl_xor_sync(0xffffffffu, s,  o);
                s2 += __shfl_xor_sync(0xffffffffu, s2, o);
            }
            if (tid == 0){
                int grp = g >> 4;
                g_gnp0[(b*2 + grp)*16 + (g & 15)] = make_float2(s, s2);
            }
        }
    }
    grid_bar_b(b);

    // ================= mamba blocks =================
    #pragma unroll 1
    for (int blk = 0; blk < 2; blk++){
        const float* w     = blk ? ip1w : ip0w;
        const float* cw    = blk ? c1w  : c0w;
        const float* cb    = blk ? c1b  : c0b;
        const float* gamma = blk ? gn1g : gn0g;
        const float* beta  = blk ? gn1b : gn0b;
        const float* xproj = blk ? xp1  : xp0;
        const float* dtw   = blk ? dt1w : dt0w;
        const float* dtb   = blk ? dt1b : dt0b;
        const float* alog  = blk ? al1  : al0;
        const float* dd    = blk ? dd1  : dd0;

        // ---------- inproj: GN + 3x3 conv + conv0+SiLU + gate + x_dbl ----------
        {
            int g = q;
            int p = tid;
            int wq = p >> 5, lane = p & 31;
            int cx0 = 2*g, cx1 = 2*g+1, cg0 = 64+2*g, cg1 = 65+2*g;
            // prefetch residual loads (independent of stats)
            float hv0 = g_h[(b*MID + cx0)*P + p];
            float hv1 = g_h[(b*MID + cx1)*P + p];
            float hv2 = g_h[(b*MID + cg0)*P + p];
            float hv3 = g_h[(b*MID + cg1)*P + p];
            if (wq < 2){
                int npart = blk ? 32 : 16;
                float2 v = make_float2(0.f, 0.f);
                if (lane < npart) v = blk ? g_gnp1[(b*2+wq)*32 + lane] : g_gnp0[(b*2+wq)*16 + lane];
                float s = v.x, s2v = v.y;
                #pragma unroll
                for (int o = 16; o; o >>= 1){
                    s   += __shfl_xor_sync(0xffffffffu, s,   o);
                    s2v += __shfl_xor_sync(0xffffffffu, s2v, o);
                }
                if (lane == 0){
                    float mean = s * (1.f/65536.f);
                    float var  = s2v * (1.f/65536.f) - mean*mean;
                    sMI[wq*2]   = mean;
                    sMI[wq*2+1] = rsqrtf(var + 1e-5f);
                }
            }
            if (p >= 64 && p < 100){
                int idx = p - 64;
                int t = idx / 4, j = idx & 3;
                float4 wv;
                wv.x = w[(4*g + j)*18 +     t];
                wv.y = w[(4*g + j)*18 + 9 + t];
                wv.z = w[(128 + 4*g + j)*18 +     t];
                wv.w = w[(128 + 4*g + j)*18 + 9 + t];
                sW4[t][j] = wv;
            }
            if (p >= 128 && p < 260){
                int i = p - 128;
                int cell;
                if (i < 34)       cell = i;
                else if (i < 68)  cell = 33*34 + (i - 34);
                else if (i < 100) cell = (i - 68 + 1)*34;
                else              cell = (i - 100 + 1)*34 + 33;
                sP[cell] = make_float4(0.f, 0.f, 0.f, 0.f);
            }
            __syncthreads();
            int y = p >> 5, xx0 = p & 31;
            {
                float m0 = sMI[0], i0 = sMI[1], m1 = sMI[2], i1 = sMI[3];
                float ga0 = gamma[cx0]*i0, be0 = beta[cx0] - m0*ga0;
                float ga1 = gamma[cx1]*i0, be1 = beta[cx1] - m0*ga1;
                float ga2 = gamma[cg0]*i1, be2 = beta[cg0] - m1*ga2;
                float ga3 = gamma[cg1]*i1, be3 = beta[cg1] - m1*ga3;
                float4 v;
                v.x = hv0*ga0 + be0;
                v.y = hv1*ga1 + be1;
                v.z = hv2*ga2 + be2;
                v.w = hv3*ga3 + be3;
                sP[(y+1)*34 + (xx0+1)] = v;
            }
            __syncthreads();
            float accx[4] = {0.f,0.f,0.f,0.f};
            float accg[4] = {0.f,0.f,0.f,0.f};
            #pragma unroll
            for (int ky = 0; ky < 3; ky++){
                #pragma unroll
                for (int kx = 0; kx < 3; kx++){
                    float4 v = sP[(y+ky)*34 + (xx0+kx)];
                    int t = ky*3 + kx;
                    #pragma unroll
                    for (int j = 0; j < 4; j++){
                        float4 W = sW4[t][j];
                        accx[j] = fmaf(v.x, W.x, fmaf(v.y, W.y, accx[j]));
                        accg[j] = fmaf(v.z, W.z, fmaf(v.w, W.w, accg[j]));
                    }
                }
            }
            #pragma unroll
            for (int j = 0; j < 4; j++){
                int c = 4*g + j;
                g_res[(b*MID + c)*P + p] = silu_f(accg[j]);
            }
            #pragma unroll
            for (int j = 0; j < 4; j++){
                int c = 4*g + j;
                float lo = (j < 2) ? accx[0] : accx[2];
                float hi = (j < 2) ? accx[1] : accx[3];
                float v = fmaf(lo, cw[c*2], fmaf(hi, cw[c*2+1], cb[c]));
                float uv = silu_f(v);
                g_u[(b*MID + c)*P + p] = uv;
                sU[j][p] = uv;
            }
            __syncthreads();
            // x_dbl rows 4g..4g+3: warp wq handles k = 3wq..3wq+2, software-pipelined loads
            const float4* xpr0 = (const float4*)(xproj + (wq*3 + 0)*P);
            const float4* xpr1 = (const float4*)(xproj + (wq*3 + 1)*P);
            const float4* xpr2 = (const float4*)(xproj + (wq*3 + 2)*P);
            const float4* u0p = (const float4*)sU[0];
            const float4* u1p = (const float4*)sU[1];
            const float4* u2p = (const float4*)sU[2];
            const float4* u3p = (const float4*)sU[3];
            float a00=0,a01=0,a02=0, a10=0,a11=0,a12=0, a20=0,a21=0,a22=0, a30=0,a31=0,a32=0;
            float4 w0n = xpr0[lane], w1n = xpr1[lane], w2n = xpr2[lane];
            #pragma unroll
            for (int i = 0; i < 8; i++){
                int px = i*32 + lane;
                float4 w0 = w0n, w1 = w1n, w2 = w2n;
                if (i < 7){
                    int pxn = px + 32;
                    w0n = xpr0[pxn]; w1n = xpr1[pxn]; w2n = xpr2[pxn];
                }
                float4 u0 = u0p[px], u1 = u1p[px], u2 = u2p[px], u3 = u3p[px];
                a00 = fmaf(u0.x,w0.x,a00); a00 = fmaf(u0.y,w0.y,a00); a00 = fmaf(u0.z,w0.z,a00); a00 = fmaf(u0.w,w0.w,a00);
                a01 = fmaf(u0.x,w1.x,a01); a01 = fmaf(u0.y,w1.y,a01); a01 = fmaf(u0.z,w1.z,a01); a01 = fmaf(u0.w,w1.w,a01);
                a02 = fmaf(u0.x,w2.x,a02); a02 = fmaf(u0.y,w2.y,a02); a02 = fmaf(u0.z,w2.z,a02); a02 = fmaf(u0.w,w2.w,a02);
                a10 = fmaf(u1.x,w0.x,a10); a10 = fmaf(u1.y,w0.y,a10); a10 = fmaf(u1.z,w0.z,a10); a10 = fmaf(u1.w,w0.w,a10);
                a11 = fmaf(u1.x,w1.x,a11); a11 = fmaf(u1.y,w1.y,a11); a11 = fmaf(u1.z,w1.z,a11); a11 = fmaf(u1.w,w1.w,a11);
                a12 = fmaf(u1.x,w2.x,a12); a12 = fmaf(u1.y,w2.y,a12); a12 = fmaf(u1.z,w2.z,a12); a12 = fmaf(u1.w,w2.w,a12);
                a20 = fmaf(u2.x,w0.x,a20); a20 = fmaf(u2.y,w0.y,a20); a20 = fmaf(u2.z,w0.z,a20); a20 = fmaf(u2.w,w0.w,a20);
                a21 = fmaf(u2.x,w1.x,a21); a21 = fmaf(u2.y,w1.y,a21); a21 = fmaf(u2.z,w1.z,a21); a21 = fmaf(u2.w,w1.w,a21);
                a22 = fmaf(u2.x,w2.x,a22); a22 = fmaf(u2.y,w2.y,a22); a22 = fmaf(u2.z,w2.z,a22); a22 = fmaf(u2.w,w2.w,a22);
                a30 = fmaf(u3.x,w0.x,a30); a30 = fmaf(u3.y,w0.y,a30); a30 = fmaf(u3.z,w0.z,a30); a30 = fmaf(u3.w,w0.w,a30);
                a31 = fmaf(u3.x,w1.x,a31); a31 = fmaf(u3.y,w1.y,a31); a31 = fmaf(u3.z,w1.z,a31); a31 = fmaf(u3.w,w1.w,a31);
                a32 = fmaf(u3.x,w2.x,a32); a32 = fmaf(u3.y,w2.y,a32); a32 = fmaf(u3.z,w2.z,a32); a32 = fmaf(u3.w,w2.w,a32);
            }
            #pragma unroll
            for (int o = 16; o; o >>= 1){
                a00 += __shfl_xor_sync(0xffffffffu, a00, o); a01 += __shfl_xor_sync(0xffffffffu, a01, o);
                a02 += __shfl_xor_sync(0xffffffffu, a02, o); a10 += __shfl_xor_sync(0xffffffffu, a10, o);
                a11 += __shfl_xor_sync(0xffffffffu, a11, o); a12 += __shfl_xor_sync(0xffffffffu, a12, o);
                a20 += __shfl_xor_sync(0xffffffffu, a20, o); a21 += __shfl_xor_sync(0xffffffffu, a21, o);
                a22 += __shfl_xor_sync(0xffffffffu, a22, o); a30 += __shfl_xor_sync(0xffffffffu, a30, o);
                a31 += __shfl_xor_sync(0xffffffffu, a31, o); a32 += __shfl_xor_sync(0xffffffffu, a32, o);
            }
            if (lane == 0){
                int k = wq*3;
                float* r0 = g_xdbl + (b*LSEQ + 4*g + 0)*KDIM + k;
                float* r1 = g_xdbl + (b*LSEQ + 4*g + 1)*KDIM + k;
                float* r2 = g_xdbl + (b*LSEQ + 4*g + 2)*KDIM + k;
                float* r3 = g_xdbl + (b*LSEQ + 4*g + 3)*KDIM + k;
                r0[0]=a00; r0[1]=a01; r0[2]=a02;
                r1[0]=a10; r1[1]=a11; r1[2]=a12;
                r2[0]=a20; r2[1]=a21; r2[2]=a22;
                r3[0]=a30; r3[1]=a31; r3[2]=a32;
            }
        }
        grid_bar_b(b);

        // ---------- scan: delta GEMM + softplus + selective scan + combine + GN1 ----------
        {
            int dt = q;
            float*  sXd = sm;                    // [128][68]; later sY overlay
            float*  sWs = sm + 8704;             // [64][33]; later GN scratch
            float*  sB  = sm + 10816;            // [128][16]
            float*  sC  = sm + 12864;            // [128][16]
            float*  sDelta = sm + 14912;         // [128][33]
            float*  sUt    = sm + 19136;         // [128][33]
            float*  sY     = sm;                 // overlay

            for (int idx = tid; idx < 128*64; idx += 1024){
                int l = idx >> 6, k = idx & 63;
                sXd[l*68 + k] = g_xdbl[(b*LSEQ + l)*KDIM + k];
            }
            for (int idx = tid; idx < 128*16; idx += 1024){
                int l = idx >> 4, n = idx & 15;
                const float* row = g_xdbl + (b*LSEQ + l)*KDIM;
                sB[l*16 + n] = row[64 + n];
                sC[l*16 + n] = row[80 + n];
            }
            for (int idx = tid; idx < 32*64; idx += 1024){
                int dl = idx >> 6, r = idx & 63;
                sWs[r*33 + dl] = dtw[(dt*32 + dl)*64 + r];
            }
            for (int idx = tid; idx < 128*32; idx += 1024){
                int l = idx >> 5, dj = idx & 31;
                sUt[l*33 + dj] = g_u[(b*LSEQ + l)*P + dt*32 + dj];
            }
            __syncthreads();

            // delta GEMM: thread = (4 l's) x (dloc)
            {
                int dloc = tid & 31, lbase = (tid >> 5) << 2;
                float acc[4] = {0.f,0.f,0.f,0.f};
                #pragma unroll
                for (int k0 = 0; k0 < 64; k0 += 16){
                    float wv[16];
                    #pragma unroll
                    for (int j = 0; j < 16; j++) wv[j] = sWs[(k0+j)*33 + dloc];
                    #pragma unroll
                    for (int l = 0; l < 4; l++){
                        const float4* row = (const float4*)(sXd + (lbase+l)*68 + k0);
                        float4 x0 = row[0], x1 = row[1], x2 = row[2], x3 = row[3];
                        float a = acc[l];
                        a = fmaf(x0.x,wv[0],a);  a = fmaf(x0.y,wv[1],a);  a = fmaf(x0.z,wv[2],a);  a = fmaf(x0.w,wv[3],a);
                        a = fmaf(x1.x,wv[4],a);  a = fmaf(x1.y,wv[5],a);  a = fmaf(x1.z,wv[6],a);  a = fmaf(x1.w,wv[7],a);
                        a = fmaf(x2.x,wv[8],a);  a = fmaf(x2.y,wv[9],a);  a = fmaf(x2.z,wv[10],a); a = fmaf(x2.w,wv[11],a);
                        a = fmaf(x3.x,wv[12],a); a = fmaf(x3.y,wv[13],a); a = fmaf(x3.z,wv[14],a); a = fmaf(x3.w,wv[15],a);
                        acc[l] = a;
                    }
                }
                float bias = dtb[dt*32 + dloc];
                #pragma unroll
                for (int l = 0; l < 4; l++){
                    float xv = acc[l] + bias;
                    sDelta[(lbase+l)*33 + dloc] = fmaxf(xv, 0.f) + __logf(1.f + __expf(-fabsf(xv)));
                }
            }
            __syncthreads();

            // scan: 256 threads, thread = (dl = tid>>3) x (n-pair = (tid&7)*2)
            if (tid < 256){
                int dl = tid >> 3;
                int np = (tid & 7) * 2;
                int d = dt*32 + dl;
                float An0 = -expf(alog[d*16 + np + 0]);
                float An1 = -expf(alog[d*16 + np + 1]);
                float Dd = dd[d];
                float cr0 = 0.f, cr1 = 0.f;
                #pragma unroll 4
                for (int l = 0; l < LSEQ; l++){
                    float td = sDelta[l*33 + dl];
                    float tu = sUt[l*33 + dl];
                    float du = td * tu;
                    float2 B2 = *(const float2*)&sB[l*16 + np];
                    float2 C2 = *(const float2*)&sC[l*16 + np];
                    cr0 = fmaf(__expf(td*An0), cr0, du*B2.x);
                    cr1 = fmaf(__expf(td*An1), cr1, du*B2.y);
                    float yv = fmaf(cr0, C2.x, cr1*C2.y);
                    yv += __shfl_xor_sync(0xffffffffu, yv, 1);
                    yv += __shfl_xor_sync(0xffffffffu, yv, 2);
                    yv += __shfl_xor_sync(0xffffffffu, yv, 4);
                    if ((tid & 7) == 0) sY[l*33 + dl] = fmaf(tu, Dd, yv);
                }
            }
            __syncthreads();

            // combine h += y*silu(res) and GN1 partial stats
            float s0 = 0.f, q0 = 0.f, s1 = 0.f, q1 = 0.f;
            for (int e = tid; e < 128*32; e += 1024){
                int l = e >> 5, dj = e & 31;
                int idx = (b*LSEQ + l)*P + dt*32 + dj;
                float h = fmaf(sY[l*33 + dj], g_res[idx], g_h[idx]);
                g_h[idx] = h;
                if (l < 64){ s0 += h; q0 += h*h; } else { s1 += h; q1 += h*h; }
            }
            if (blk == 0){
                #pragma unroll
                for (int o = 16; o; o >>= 1){
                    s0 += __shfl_xor_sync(0xffffffffu, s0, o);
                    q0 += __shfl_xor_sync(0xffffffffu, q0, o);
                    s1 += __shfl_xor_sync(0xffffffffu, s1, o);
                    q1 += __shfl_xor_sync(0xffffffffu, q1, o);
                }
                int wid = tid >> 5;
                __syncthreads();
                if ((tid & 31) == 0){
                    sWs[wid*4+0] = s0; sWs[wid*4+1] = q0; sWs[wid*4+2] = s1; sWs[wid*4+3] = q1;
                }
                __syncthreads();
                if (tid == 0){
                    float S0=0,Q0=0,S1=0,Q1=0;
                    #pragma unroll
                    for (int i = 0; i < 32; i++){ S0+=sWs[i*4]; Q0+=sWs[i*4+1]; S1+=sWs[i*4+2]; Q1+=sWs[i*4+3]; }
                    g_gnp1[(b*2 + 0)*32 + dt] = make_float2(S0, Q0);
                    g_gnp1[(b*2 + 1)*32 + dt] = make_float2(S1, Q1);
                }
            }
        }
        grid_bar_b(b);
    }

    // ================= conv_out + x8 bilinear upsample (4 planes per block) =================
    {
        int lane64 = tid & 63;
        int ry2 = tid >> 6;                 // 0..15
        int ii = lane64 >> 1;               // source col 0..31
        int jh = lane64 & 1;                // which half of the 8-wide output group
        int ca = jh ? ii : (ii > 0 ? ii - 1 : 0);
        int cbx = jh ? (ii < 31 ? ii + 1 : 31) : ii;
        float wxa = jh ? 0.0625f : 0.5625f;
        #pragma unroll 1
        for (int i = 0; i < 4; i++){
            int plane = bid*4 + i;
            int pb = plane >> 7, oc = plane & 127;
            int g = oc >> 2;
            const float* hb = g_h + (size_t)(pb*MID + 4*g)*P;
            if (tid < 256){
                float w0 = wout[oc*4], w1 = wout[oc*4+1], w2 = wout[oc*4+2], w3 = wout[oc*4+3];
                float bias = bout[oc];
                float4 a  = ((const float4*)hb)[tid];
                float4 c1 = ((const float4*)(hb+P))[tid];
                float4 c2 = ((const float4*)(hb+2*P))[tid];
                float4 c3 = ((const float4*)(hb+3*P))[tid];
                float4 r;
                r.x = bias + a.x*w0 + c1.x*w1 + c2.x*w2 + c3.x*w3;
                r.y = bias + a.y*w0 + c1.y*w1 + c2.y*w2 + c3.y*w3;
                r.z = bias + a.z*w0 + c1.z*w1 + c2.z*w2 + c3.z*w3;
                r.w = bias + a.w*w0 + c1.w*w1 + c2.w*w2 + c3.w*w3;
                ((float4*)sCo)[tid] = r;
            }
            __syncthreads();
            float* obase = out + ((size_t)(pb*MID + oc))*256*256;
            #pragma unroll 4
            for (int t = 0; t < 16; t++){
                int oy = t*16 + ry2;
                float sy = (oy + 0.5f) * 0.125f - 0.5f;
                int iy = (int)floorf(sy);
                float fy = sy - (float)iy;
                int iy0 = iy < 0 ? 0 : iy;
                int iy1 = (iy + 1 > 31) ? 31 : iy + 1;
                const float* r0 = sCo + iy0*32;
                const float* r1 = sCo + iy1*32;
                float a0 = r0[ca], a1 = r1[ca];
                float b0 = r0[cbx], b1 = r1[cbx];
                float va = a0 + (a1 - a0) * fy;
                float vb = b0 + (b1 - b0) * fy;
                float dab = vb - va;
                float4 v;
                v.x = fmaf(dab, wxa,            va);
                v.y = fmaf(dab, wxa + 0.125f,   va);
                v.z = fmaf(dab, wxa + 0.25f,    va);
                v.w = fmaf(dab, wxa + 0.375f,   va);
                ((float4*)(obase + oy*256))[lane64] = v;
            }
            __syncthreads();
        }
    }
}

// ---------------- host orchestration ----------------
extern "C" void kernel_launch(void* const* d_in, const int* in_sizes, int n_in,
                              void* d_out, int out_size){
    cudaFuncSetAttribute(k_mega, cudaFuncAttributeMaxDynamicSharedMemorySize, SCAN_SMEM_BYTES);

    k_mega<<<NBLK, 1024, SCAN_SMEM_BYTES>>>(
        (const float*)d_in[0],  (const float*)d_in[1],  (const float*)d_in[2],
        (const float*)d_in[3],  (const float*)d_in[4],  (const float*)d_in[5],
        (const float*)d_in[6],  (const float*)d_in[7],  (const float*)d_in[8],
        (const float*)d_in[9],  (const float*)d_in[10], (const float*)d_in[11],
        (const float*)d_in[12],
        (const float*)d_in[13], (const float*)d_in[14], (const float*)d_in[15],
        (const float*)d_in[16], (const float*)d_in[17], (const float*)d_in[18],
        (const float*)d_in[19], (const float*)d_in[20], (const float*)d_in[21],
        (const float*)d_in[22],
        (const float*)d_in[23], (const float*)d_in[24], (float*)d_out);
}

// round 16
// speedup vs baseline: 1.1388x; 1.0568x over previous
#include <cuda_runtime.h>
#include <cuda_bf16.h>
#include <math.h>

// ---------------- problem constants ----------------
#define BATCH 4
#define CIN   64
#define HH    256
#define WW    256
#define MID   128
#define P     1024
#define LSEQ  128
#define NST   16
#define KDIM  96
#define NBLK  128
#define NBLK_B 32

// ---------------- device scratch ----------------
__device__ float  g_h[BATCH*MID*P];
__device__ float  g_u[BATCH*MID*P];
__device__ float  g_res[BATCH*MID*P];
__device__ __align__(16) float g_xdbl[BATCH*LSEQ*KDIM];
__device__ float2 g_gnp0[BATCH*2*16];
__device__ float2 g_gnp1[BATCH*2*32];

// per-batch grid barrier state (generation-based; monotonic across graph replays)
__device__ volatile unsigned g_gen[BATCH];
__device__ unsigned g_cnt[BATCH];

__device__ __forceinline__ void grid_bar_b(int b){
    __syncthreads();
    if (threadIdx.x == 0){
        __threadfence();
        unsigned old = g_gen[b];
        unsigned rank = atomicAdd(&g_cnt[b], 1u);
        if (rank == NBLK_B - 1){
            g_cnt[b] = 0;
            __threadfence();
            atomicAdd((unsigned*)&g_gen[b], 1u);
        } else {
            while (g_gen[b] == old) { __nanosleep(32); }
        }
        __threadfence();
    }
    __syncthreads();
}

__device__ __forceinline__ float silu_f(float v){ return v / (1.f + __expf(-v)); }

#define SCAN_SMEM_FLOATS 23360
#define SCAN_SMEM_BYTES  (SCAN_SMEM_FLOATS*4)

// =========================== MEGA KERNEL ===========================
__global__ void __launch_bounds__(1024, 1)
k_mega(const float* __restrict__ x, const float* __restrict__ w_in, const float* __restrict__ b_in,
       const float* __restrict__ gn0g, const float* __restrict__ gn0b, const float* __restrict__ ip0w,
       const float* __restrict__ c0w,  const float* __restrict__ c0b,  const float* __restrict__ xp0,
       const float* __restrict__ dt0w, const float* __restrict__ dt0b, const float* __restrict__ al0,
       const float* __restrict__ dd0,
       const float* __restrict__ gn1g, const float* __restrict__ gn1b, const float* __restrict__ ip1w,
       const float* __restrict__ c1w,  const float* __restrict__ c1b,  const float* __restrict__ xp1,
       const float* __restrict__ dt1w, const float* __restrict__ dt1b, const float* __restrict__ al1,
       const float* __restrict__ dd1,
       const float* __restrict__ wout, const float* __restrict__ bout, float* __restrict__ out)
{
    extern __shared__ float sm[];   // scan workspace (93 KB)
    __shared__ __align__(16) float4 sP[34*34];
    __shared__ __align__(16) float  sU[4][P];
    __shared__ __align__(16) float4 sW4[9][4];
    __shared__ float sMI[4];
    __shared__ float swdc[4][2][8][8];
    __shared__ float red[64];
    __shared__ __align__(16) float sCo[1024];

    int bid = blockIdx.x;
    int b = bid >> 5, q = bid & 31;     // q = group/dtile index
    int tid = threadIdx.x;

    // ================= phase 0: downconv (8x8 stride 8) + GN0 stats =================
    {
        int g = q;
        int ty = tid >> 5, tx = tid & 31;
        if (tid < 512){
            int oc4 = tid >> 7, rem = tid & 127;
            swdc[oc4][rem>>6][(rem>>3)&7][rem&7] = w_in[(4*g + oc4)*128 + rem];
        }
        __syncthreads();
        float acc0=0.f, acc1=0.f, acc2=0.f, acc3=0.f;
        #pragma unroll
        for (int ic = 0; ic < 2; ic++){
            const float* xb = x + (((size_t)b*CIN + 2*g + ic)*HH + ty*8)*WW + tx*8;
            #pragma unroll
            for (int ky = 0; ky < 8; ky++){
                const float4* r = (const float4*)(xb + ky*WW);
                float4 v0 = r[0], v1 = r[1];
                float xv[8] = {v0.x,v0.y,v0.z,v0.w,v1.x,v1.y,v1.z,v1.w};
                #pragma unroll
                for (int kx = 0; kx < 8; kx++){
                    float xvv = xv[kx];
                    acc0 = fmaf(xvv, swdc[0][ic][ky][kx], acc0);
                    acc1 = fmaf(xvv, swdc[1][ic][ky][kx], acc1);
                    acc2 = fmaf(xvv, swdc[2][ic][ky][kx], acc2);
                    acc3 = fmaf(xvv, swdc[3][ic][ky][kx], acc3);
                }
            }
        }
        acc0 += b_in[4*g+0]; acc1 += b_in[4*g+1]; acc2 += b_in[4*g+2]; acc3 += b_in[4*g+3];
        int p = ty*32 + tx;
        g_h[(b*MID + 4*g + 0)*P + p] = acc0;
        g_h[(b*MID + 4*g + 1)*P + p] = acc1;
        g_h[(b*MID + 4*g + 2)*P + p] = acc2;
        g_h[(b*MID + 4*g + 3)*P + p] = acc3;
        float s  = acc0 + acc1 + acc2 + acc3;
        float s2 = acc0*acc0 + acc1*acc1 + acc2*acc2 + acc3*acc3;
        #pragma unroll
        for (int o = 16; o; o >>= 1){
            s  += __shfl_xor_sync(0xffffffffu, s,  o);
            s2 += __shfl_xor_sync(0xffffffffu, s2, o);
        }
        int wid = tid >> 5, lid = tid & 31;
        if (lid == 0){ red[wid] = s; red[32+wid] = s2; }
        __syncthreads();
        if (tid < 32){
            s = red[tid]; s2 = red[32+tid];
            #pragma unroll
            for (int o = 16; o; o >>= 1){
                s  += __shfl_xor_sync(0xffffffffu, s,  o);
                s2 += __shfl_xor_sync(0xffffffffu, s2, o);
            }
            if (tid == 0){
                int grp = g >> 4;
                g_gnp0[(b*2 + grp)*16 + (g & 15)] = make_float2(s, s2);
            }
        }
    }
    grid_bar_b(b);

    // ================= mamba blocks =================
    #pragma unroll 1
    for (int blk = 0; blk < 2; blk++){
        const float* w     = blk ? ip1w : ip0w;
        const float* cw    = blk ? c1w  : c0w;
        const float* cb    = blk ? c1b  : c0b;
        const float* gamma = blk ? gn1g : gn0g;
        const float* beta  = blk ? gn1b : gn0b;
        const float* xproj = blk ? xp1  : xp0;
        const float* dtw   = blk ? dt1w : dt0w;
        const float* dtb   = blk ? dt1b : dt0b;
        const float* alog  = blk ? al1  : al0;
        const float* dd    = blk ? dd1  : dd0;

        // ---------- inproj: GN + 3x3 conv + conv0+SiLU + gate + x_dbl ----------
        {
            int g = q;
            int p = tid;
            int wq = p >> 5, lane = p & 31;
            int cx0 = 2*g, cx1 = 2*g+1, cg0 = 64+2*g, cg1 = 65+2*g;
            // prefetch residual loads (independent of stats)
            float hv0 = g_h[(b*MID + cx0)*P + p];
            float hv1 = g_h[(b*MID + cx1)*P + p];
            float hv2 = g_h[(b*MID + cg0)*P + p];
            float hv3 = g_h[(b*MID + cg1)*P + p];
            if (wq < 2){
                int npart = blk ? 32 : 16;
                float2 v = make_float2(0.f, 0.f);
                if (lane < npart) v = blk ? g_gnp1[(b*2+wq)*32 + lane] : g_gnp0[(b*2+wq)*16 + lane];
                float s = v.x, s2v = v.y;
                #pragma unroll
                for (int o = 16; o; o >>= 1){
                    s   += __shfl_xor_sync(0xffffffffu, s,   o);
                    s2v += __shfl_xor_sync(0xffffffffu, s2v, o);
                }
                if (lane == 0){
                    float mean = s * (1.f/65536.f);
                    float var  = s2v * (1.f/65536.f) - mean*mean;
                    sMI[wq*2]   = mean;
                    sMI[wq*2+1] = rsqrtf(var + 1e-5f);
                }
            }
            if (p >= 64 && p < 100){
                int idx = p - 64;
                int t = idx / 4, j = idx & 3;
                float4 wv;
                wv.x = w[(4*g + j)*18 +     t];
                wv.y = w[(4*g + j)*18 + 9 + t];
                wv.z = w[(128 + 4*g + j)*18 +     t];
                wv.w = w[(128 + 4*g + j)*18 + 9 + t];
                sW4[t][j] = wv;
            }
            if (p >= 128 && p < 260){
                int i = p - 128;
                int cell;
                if (i < 34)       cell = i;
                else if (i < 68)  cell = 33*34 + (i - 34);
                else if (i < 100) cell = (i - 68 + 1)*34;
                else              cell = (i - 100 + 1)*34 + 33;
                sP[cell] = make_float4(0.f, 0.f, 0.f, 0.f);
            }
            __syncthreads();
            int y = p >> 5, xx0 = p & 31;
            {
                float m0 = sMI[0], i0 = sMI[1], m1 = sMI[2], i1 = sMI[3];
                float ga0 = gamma[cx0]*i0, be0 = beta[cx0] - m0*ga0;
                float ga1 = gamma[cx1]*i0, be1 = beta[cx1] - m0*ga1;
                float ga2 = gamma[cg0]*i1, be2 = beta[cg0] - m1*ga2;
                float ga3 = gamma[cg1]*i1, be3 = beta[cg1] - m1*ga3;
                float4 v;
                v.x = hv0*ga0 + be0;
                v.y = hv1*ga1 + be1;
                v.z = hv2*ga2 + be2;
                v.w = hv3*ga3 + be3;
                sP[(y+1)*34 + (xx0+1)] = v;
            }
            __syncthreads();
            float accx[4] = {0.f,0.f,0.f,0.f};
            float accg[4] = {0.f,0.f,0.f,0.f};
            #pragma unroll
            for (int ky = 0; ky < 3; ky++){
                #pragma unroll
                for (int kx = 0; kx < 3; kx++){
                    float4 v = sP[(y+ky)*34 + (xx0+kx)];
                    int t = ky*3 + kx;
                    #pragma unroll
                    for (int j = 0; j < 4; j++){
                        float4 W = sW4[t][j];
                        accx[j] = fmaf(v.x, W.x, fmaf(v.y, W.y, accx[j]));
                        accg[j] = fmaf(v.z, W.z, fmaf(v.w, W.w, accg[j]));
                    }
                }
            }
            #pragma unroll
            for (int j = 0; j < 4; j++){
                int c = 4*g + j;
                g_res[(b*MID + c)*P + p] = silu_f(accg[j]);
            }
            #pragma unroll
            for (int j = 0; j < 4; j++){
                int c = 4*g + j;
                float lo = (j < 2) ? accx[0] : accx[2];
                float hi = (j < 2) ? accx[1] : accx[3];
                float v = fmaf(lo, cw[c*2], fmaf(hi, cw[c*2+1], cb[c]));
                float uv = silu_f(v);
                g_u[(b*MID + c)*P + p] = uv;
                sU[j][p] = uv;
            }
            __syncthreads();
            // x_dbl rows 4g..4g+3: warp wq handles k = 3wq..3wq+2, software-pipelined loads
            const float4* xpr0 = (const float4*)(xproj + (wq*3 + 0)*P);
            const float4* xpr1 = (const float4*)(xproj + (wq*3 + 1)*P);
            const float4* xpr2 = (const float4*)(xproj + (wq*3 + 2)*P);
            const float4* u0p = (const float4*)sU[0];
            const float4* u1p = (const float4*)sU[1];
            const float4* u2p = (const float4*)sU[2];
            const float4* u3p = (const float4*)sU[3];
            float a00=0,a01=0,a02=0, a10=0,a11=0,a12=0, a20=0,a21=0,a22=0, a30=0,a31=0,a32=0;
            float4 w0n = xpr0[lane], w1n = xpr1[lane], w2n = xpr2[lane];
            #pragma unroll
            for (int i = 0; i < 8; i++){
                int px = i*32 + lane;
                float4 w0 = w0n, w1 = w1n, w2 = w2n;
                if (i < 7){
                    int pxn = px + 32;
                    w0n = xpr0[pxn]; w1n = xpr1[pxn]; w2n = xpr2[pxn];
                }
                float4 u0 = u0p[px], u1 = u1p[px], u2 = u2p[px], u3 = u3p[px];
                a00 = fmaf(u0.x,w0.x,a00); a00 = fmaf(u0.y,w0.y,a00); a00 = fmaf(u0.z,w0.z,a00); a00 = fmaf(u0.w,w0.w,a00);
                a01 = fmaf(u0.x,w1.x,a01); a01 = fmaf(u0.y,w1.y,a01); a01 = fmaf(u0.z,w1.z,a01); a01 = fmaf(u0.w,w1.w,a01);
                a02 = fmaf(u0.x,w2.x,a02); a02 = fmaf(u0.y,w2.y,a02); a02 = fmaf(u0.z,w2.z,a02); a02 = fmaf(u0.w,w2.w,a02);
                a10 = fmaf(u1.x,w0.x,a10); a10 = fmaf(u1.y,w0.y,a10); a10 = fmaf(u1.z,w0.z,a10); a10 = fmaf(u1.w,w0.w,a10);
                a11 = fmaf(u1.x,w1.x,a11); a11 = fmaf(u1.y,w1.y,a11); a11 = fmaf(u1.z,w1.z,a11); a11 = fmaf(u1.w,w1.w,a11);
                a12 = fmaf(u1.x,w2.x,a12); a12 = fmaf(u1.y,w2.y,a12); a12 = fmaf(u1.z,w2.z,a12); a12 = fmaf(u1.w,w2.w,a12);
                a20 = fmaf(u2.x,w0.x,a20); a20 = fmaf(u2.y,w0.y,a20); a20 = fmaf(u2.z,w0.z,a20); a20 = fmaf(u2.w,w0.w,a20);
                a21 = fmaf(u2.x,w1.x,a21); a21 = fmaf(u2.y,w1.y,a21); a21 = fmaf(u2.z,w1.z,a21); a21 = fmaf(u2.w,w1.w,a21);
                a22 = fmaf(u2.x,w2.x,a22); a22 = fmaf(u2.y,w2.y,a22); a22 = fmaf(u2.z,w2.z,a22); a22 = fmaf(u2.w,w2.w,a22);
                a30 = fmaf(u3.x,w0.x,a30); a30 = fmaf(u3.y,w0.y,a30); a30 = fmaf(u3.z,w0.z,a30); a30 = fmaf(u3.w,w0.w,a30);
                a31 = fmaf(u3.x,w1.x,a31); a31 = fmaf(u3.y,w1.y,a31); a31 = fmaf(u3.z,w1.z,a31); a31 = fmaf(u3.w,w1.w,a31);
                a32 = fmaf(u3.x,w2.x,a32); a32 = fmaf(u3.y,w2.y,a32); a32 = fmaf(u3.z,w2.z,a32); a32 = fmaf(u3.w,w2.w,a32);
            }
            #pragma unroll
            for (int o = 16; o; o >>= 1){
                a00 += __shfl_xor_sync(0xffffffffu, a00, o); a01 += __shfl_xor_sync(0xffffffffu, a01, o);
                a02 += __shfl_xor_sync(0xffffffffu, a02, o); a10 += __shfl_xor_sync(0xffffffffu, a10, o);
                a11 += __shfl_xor_sync(0xffffffffu, a11, o); a12 += __shfl_xor_sync(0xffffffffu, a12, o);
                a20 += __shfl_xor_sync(0xffffffffu, a20, o); a21 += __shfl_xor_sync(0xffffffffu, a21, o);
                a22 += __shfl_xor_sync(0xffffffffu, a22, o); a30 += __shfl_xor_sync(0xffffffffu, a30, o);
                a31 += __shfl_xor_sync(0xffffffffu, a31, o); a32 += __shfl_xor_sync(0xffffffffu, a32, o);
            }
            if (lane == 0){
                int k = wq*3;
                float* r0 = g_xdbl + (b*LSEQ + 4*g + 0)*KDIM + k;
                float* r1 = g_xdbl + (b*LSEQ + 4*g + 1)*KDIM + k;
                float* r2 = g_xdbl + (b*LSEQ + 4*g + 2)*KDIM + k;
                float* r3 = g_xdbl + (b*LSEQ + 4*g + 3)*KDIM + k;
                r0[0]=a00; r0[1]=a01; r0[2]=a02;
                r1[0]=a10; r1[1]=a11; r1[2]=a12;
                r2[0]=a20; r2[1]=a21; r2[2]=a22;
                r3[0]=a30; r3[1]=a31; r3[2]=a32;
            }
        }
        grid_bar_b(b);

        // ---------- scan: delta GEMM + softplus + selective scan + combine + GN1 ----------
        {
            int dt = q;
            float*  sXd = sm;                    // [128][68]; later sY overlay
            float*  sWs = sm + 8704;             // [64][33]; later GN scratch
            float*  sB  = sm + 10816;            // [128][16]
            float*  sC  = sm + 12864;            // [128][16]
            float*  sDelta = sm + 14912;         // [128][33]
            float*  sUt    = sm + 19136;         // [128][33]
            float*  sY     = sm;                 // overlay

            for (int idx = tid; idx < 128*64; idx += 1024){
                int l = idx >> 6, k = idx & 63;
                sXd[l*68 + k] = g_xdbl[(b*LSEQ + l)*KDIM + k];
            }
            for (int idx = tid; idx < 128*16; idx += 1024){
                int l = idx >> 4, n = idx & 15;
                const float* row = g_xdbl + (b*LSEQ + l)*KDIM;
                sB[l*16 + n] = row[64 + n];
                sC[l*16 + n] = row[80 + n];
            }
            for (int idx = tid; idx < 32*64; idx += 1024){
                int dl = idx >> 6, r = idx & 63;
                sWs[r*33 + dl] = dtw[(dt*32 + dl)*64 + r];
            }
            for (int idx = tid; idx < 128*32; idx += 1024){
                int l = idx >> 5, dj = idx & 31;
                sUt[l*33 + dj] = g_u[(b*LSEQ + l)*P + dt*32 + dj];
            }
            __syncthreads();

            // delta GEMM: thread = (4 l's) x (dloc)
            {
                int dloc = tid & 31, lbase = (tid >> 5) << 2;
                float acc[4] = {0.f,0.f,0.f,0.f};
                #pragma unroll
                for (int k0 = 0; k0 < 64; k0 += 16){
                    float wv[16];
                    #pragma unroll
                    for (int j = 0; j < 16; j++) wv[j] = sWs[(k0+j)*33 + dloc];
                    #pragma unroll
                    for (int l = 0; l < 4; l++){
                        const float4* row = (const float4*)(sXd + (lbase+l)*68 + k0);
                        float4 x0 = row[0], x1 = row[1], x2 = row[2], x3 = row[3];
                        float a = acc[l];
                        a = fmaf(x0.x,wv[0],a);  a = fmaf(x0.y,wv[1],a);  a = fmaf(x0.z,wv[2],a);  a = fmaf(x0.w,wv[3],a);
                        a = fmaf(x1.x,wv[4],a);  a = fmaf(x1.y,wv[5],a);  a = fmaf(x1.z,wv[6],a);  a = fmaf(x1.w,wv[7],a);
                        a = fmaf(x2.x,wv[8],a);  a = fmaf(x2.y,wv[9],a);  a = fmaf(x2.z,wv[10],a); a = fmaf(x2.w,wv[11],a);
                        a = fmaf(x3.x,wv[12],a); a = fmaf(x3.y,wv[13],a); a = fmaf(x3.z,wv[14],a); a = fmaf(x3.w,wv[15],a);
                        acc[l] = a;
                    }
                }
                float bias = dtb[dt*32 + dloc];
                #pragma unroll
                for (int l = 0; l < 4; l++){
                    float xv = acc[l] + bias;
                    sDelta[(lbase+l)*33 + dloc] = fmaxf(xv, 0.f) + __logf(1.f + __expf(-fabsf(xv)));
                }
            }
            __syncthreads();

            // scan: 128 threads, thread = (dl = tid>>2) x (n-quad = (tid&3)*4), prefetched
            if (tid < 128){
                int dl = tid >> 2;
                int nq = (tid & 3) * 4;
                int d = dt*32 + dl;
                float An0 = -expf(alog[d*16 + nq + 0]);
                float An1 = -expf(alog[d*16 + nq + 1]);
                float An2 = -expf(alog[d*16 + nq + 2]);
                float An3 = -expf(alog[d*16 + nq + 3]);
                float Dd = dd[d];
                float cr0 = 0.f, cr1 = 0.f, cr2 = 0.f, cr3 = 0.f;
                float td_n = sDelta[dl];
                float tu_n = sUt[dl];
                float4 B4n = *(const float4*)&sB[nq];
                float4 C4n = *(const float4*)&sC[nq];
                #pragma unroll 4
                for (int l = 0; l < LSEQ; l++){
                    float td = td_n, tu = tu_n;
                    float4 B4 = B4n, C4 = C4n;
                    if (l < LSEQ-1){
                        td_n = sDelta[(l+1)*33 + dl];
                        tu_n = sUt[(l+1)*33 + dl];
                        B4n = *(const float4*)&sB[(l+1)*16 + nq];
                        C4n = *(const float4*)&sC[(l+1)*16 + nq];
                    }
                    float du = td * tu;
                    cr0 = fmaf(__expf(td*An0), cr0, du*B4.x);
                    cr1 = fmaf(__expf(td*An1), cr1, du*B4.y);
                    cr2 = fmaf(__expf(td*An2), cr2, du*B4.z);
                    cr3 = fmaf(__expf(td*An3), cr3, du*B4.w);
                    float yv = fmaf(cr0, C4.x, fmaf(cr1, C4.y, fmaf(cr2, C4.z, cr3*C4.w)));
                    yv += __shfl_xor_sync(0xffffffffu, yv, 1);
                    yv += __shfl_xor_sync(0xffffffffu, yv, 2);
                    if ((tid & 3) == 0) sY[l*33 + dl] = fmaf(tu, Dd, yv);
                }
            }
            __syncthreads();

            // combine h += y*silu(res) and GN1 partial stats
            float s0 = 0.f, q0 = 0.f, s1 = 0.f, q1 = 0.f;
            for (int e = tid; e < 128*32; e += 1024){
                int l = e >> 5, dj = e & 31;
                int idx = (b*LSEQ + l)*P + dt*32 + dj;
                float h = fmaf(sY[l*33 + dj], g_res[idx], g_h[idx]);
                g_h[idx] = h;
                if (l < 64){ s0 += h; q0 += h*h; } else { s1 += h; q1 += h*h; }
            }
            if (blk == 0){
                #pragma unroll
                for (int o = 16; o; o >>= 1){
                    s0 += __shfl_xor_sync(0xffffffffu, s0, o);
                    q0 += __shfl_xor_sync(0xffffffffu, q0, o);
                    s1 += __shfl_xor_sync(0xffffffffu, s1, o);
                    q1 += __shfl_xor_sync(0xffffffffu, q1, o);
                }
                int wid = tid >> 5;
                __syncthreads();
                if ((tid & 31) == 0){
                    sWs[wid*4+0] = s0; sWs[wid*4+1] = q0; sWs[wid*4+2] = s1; sWs[wid*4+3] = q1;
                }
                __syncthreads();
                if (tid == 0){
                    float S0=0,Q0=0,S1=0,Q1=0;
                    #pragma unroll
                    for (int i = 0; i < 32; i++){ S0+=sWs[i*4]; Q0+=sWs[i*4+1]; S1+=sWs[i*4+2]; Q1+=sWs[i*4+3]; }
                    g_gnp1[(b*2 + 0)*32 + dt] = make_float2(S0, Q0);
                    g_gnp1[(b*2 + 1)*32 + dt] = make_float2(S1, Q1);
                }
            }
        }
        grid_bar_b(b);
    }

    // ================= conv_out + x8 bilinear upsample (4 planes per block) =================
    {
        int lane64 = tid & 63;
        int ry2 = tid >> 6;                 // 0..15
        int ii = lane64 >> 1;               // source col 0..31
        int jh = lane64 & 1;                // which half of the 8-wide output group
        int ca = jh ? ii : (ii > 0 ? ii - 1 : 0);
        int cbx = jh ? (ii < 31 ? ii + 1 : 31) : ii;
        float wxa = jh ? 0.0625f : 0.5625f;
        #pragma unroll 1
        for (int i = 0; i < 4; i++){
            int plane = bid*4 + i;
            int pb = plane >> 7, oc = plane & 127;
            int g = oc >> 2;
            const float* hb = g_h + (size_t)(pb*MID + 4*g)*P;
            if (tid < 256){
                float w0 = wout[oc*4], w1 = wout[oc*4+1], w2 = wout[oc*4+2], w3 = wout[oc*4+3];
                float bias = bout[oc];
                float4 a  = ((const float4*)hb)[tid];
                float4 c1 = ((const float4*)(hb+P))[tid];
                float4 c2 = ((const float4*)(hb+2*P))[tid];
                float4 c3 = ((const float4*)(hb+3*P))[tid];
                float4 r;
                r.x = bias + a.x*w0 + c1.x*w1 + c2.x*w2 + c3.x*w3;
                r.y = bias + a.y*w0 + c1.y*w1 + c2.y*w2 + c3.y*w3;
                r.z = bias + a.z*w0 + c1.z*w1 + c2.z*w2 + c3.z*w3;
                r.w = bias + a.w*w0 + c1.w*w1 + c2.w*w2 + c3.w*w3;
                ((float4*)sCo)[tid] = r;
            }
            __syncthreads();
            float* obase = out + ((size_t)(pb*MID + oc))*256*256;
            #pragma unroll 4
            for (int t = 0; t < 16; t++){
                int oy = t*16 + ry2;
                float sy = (oy + 0.5f) * 0.125f - 0.5f;
                int iy = (int)floorf(sy);
                float fy = sy - (float)iy;
                int iy0 = iy < 0 ? 0 : iy;
                int iy1 = (iy + 1 > 31) ? 31 : iy + 1;
                const float* r0 = sCo + iy0*32;
                const float* r1 = sCo + iy1*32;
                float a0 = r0[ca], a1 = r1[ca];
                float b0 = r0[cbx], b1 = r1[cbx];
                float va = a0 + (a1 - a0) * fy;
                float vb = b0 + (b1 - b0) * fy;
                float dab = vb - va;
                float4 v;
                v.x = fmaf(dab, wxa,            va);
                v.y = fmaf(dab, wxa + 0.125f,   va);
                v.z = fmaf(dab, wxa + 0.25f,    va);
                v.w = fmaf(dab, wxa + 0.375f,   va);
                ((float4*)(obase + oy*256))[lane64] = v;
            }
            __syncthreads();
        }
    }
}

// ---------------- host orchestration ----------------
extern "C" void kernel_launch(void* const* d_in, const int* in_sizes, int n_in,
                              void* d_out, int out_size){
    cudaFuncSetAttribute(k_mega, cudaFuncAttributeMaxDynamicSharedMemorySize, SCAN_SMEM_BYTES);

    k_mega<<<NBLK, 1024, SCAN_SMEM_BYTES>>>(
        (const float*)d_in[0],  (const float*)d_in[1],  (const float*)d_in[2],
        (const float*)d_in[3],  (const float*)d_in[4],  (const float*)d_in[5],
        (const float*)d_in[6],  (const float*)d_in[7],  (const float*)d_in[8],
        (const float*)d_in[9],  (const float*)d_in[10], (const float*)d_in[11],
        (const float*)d_in[12],
        (const float*)d_in[13], (const float*)d_in[14], (const float*)d_in[15],
        (const float*)d_in[16], (const float*)d_in[17], (const float*)d_in[18],
        (const float*)d_in[19], (const float*)d_in[20], (const float*)d_in[21],
        (const float*)d_in[22],
        (const float*)d_in[23], (const float*)d_in[24], (float*)d_out);
}

// round 17
// speedup vs baseline: 1.1566x; 1.0157x over previous
#include <cuda_runtime.h>
#include <cuda_bf16.h>
#include <math.h>

// ---------------- problem constants ----------------
#define BATCH 4
#define CIN   64
#define HH    256
#define WW    256
#define MID   128
#define P     1024
#define LSEQ  128
#define NST   16
#define KDIM  96
#define NBLK  128
#define NBLK_B 32

// ---------------- device scratch ----------------
__device__ float  g_h[BATCH*MID*P];
__device__ float  g_u[BATCH*MID*P];
__device__ float  g_res[BATCH*MID*P];
__device__ __align__(16) float g_xdbl[BATCH*LSEQ*KDIM];
__device__ float2 g_gnp0[BATCH*2*16];
__device__ float2 g_gnp1[BATCH*2*32];

// per-batch grid barrier state (generation-based; monotonic across graph replays)
__device__ volatile unsigned g_gen[BATCH];
__device__ unsigned g_cnt[BATCH];

__device__ __forceinline__ void grid_bar_b(int b){
    __syncthreads();
    if (threadIdx.x == 0){
        __threadfence();
        unsigned old = g_gen[b];
        unsigned rank = atomicAdd(&g_cnt[b], 1u);
        if (rank == NBLK_B - 1){
            g_cnt[b] = 0;
            __threadfence();
            atomicAdd((unsigned*)&g_gen[b], 1u);
        } else {
            while (g_gen[b] == old) { __nanosleep(32); }
        }
        __threadfence();
    }
    __syncthreads();
}

__device__ __forceinline__ float silu_f(float v){ return v / (1.f + __expf(-v)); }

#define SCAN_SMEM_FLOATS 23360
#define SCAN_SMEM_BYTES  (SCAN_SMEM_FLOATS*4)

// =========================== MEGA KERNEL ===========================
__global__ void __launch_bounds__(1024, 1)
k_mega(const float* __restrict__ x, const float* __restrict__ w_in, const float* __restrict__ b_in,
       const float* __restrict__ gn0g, const float* __restrict__ gn0b, const float* __restrict__ ip0w,
       const float* __restrict__ c0w,  const float* __restrict__ c0b,  const float* __restrict__ xp0,
       const float* __restrict__ dt0w, const float* __restrict__ dt0b, const float* __restrict__ al0,
       const float* __restrict__ dd0,
       const float* __restrict__ gn1g, const float* __restrict__ gn1b, const float* __restrict__ ip1w,
       const float* __restrict__ c1w,  const float* __restrict__ c1b,  const float* __restrict__ xp1,
       const float* __restrict__ dt1w, const float* __restrict__ dt1b, const float* __restrict__ al1,
       const float* __restrict__ dd1,
       const float* __restrict__ wout, const float* __restrict__ bout, float* __restrict__ out)
{
    extern __shared__ float sm[];   // scan workspace (93 KB)
    __shared__ __align__(16) float4 sP[34*34];
    __shared__ __align__(16) float  sU[4][P];
    __shared__ __align__(16) float4 sW4[9][4];
    __shared__ float sMI[4];
    __shared__ float swdc[4][2][8][8];
    __shared__ float red[64];
    __shared__ __align__(16) float sCo[1024];

    int bid = blockIdx.x;
    int b = bid >> 5, q = bid & 31;     // q = group/dtile index
    int tid = threadIdx.x;

    // ================= phase 0: downconv (8x8 stride 8) + GN0 stats =================
    {
        int g = q;
        int ty = tid >> 5, tx = tid & 31;
        if (tid < 512){
            int oc4 = tid >> 7, rem = tid & 127;
            swdc[oc4][rem>>6][(rem>>3)&7][rem&7] = w_in[(4*g + oc4)*128 + rem];
        }
        __syncthreads();
        float acc0=0.f, acc1=0.f, acc2=0.f, acc3=0.f;
        #pragma unroll
        for (int ic = 0; ic < 2; ic++){
            const float* xb = x + (((size_t)b*CIN + 2*g + ic)*HH + ty*8)*WW + tx*8;
            #pragma unroll
            for (int ky = 0; ky < 8; ky++){
                const float4* r = (const float4*)(xb + ky*WW);
                float4 v0 = r[0], v1 = r[1];
                float xv[8] = {v0.x,v0.y,v0.z,v0.w,v1.x,v1.y,v1.z,v1.w};
                #pragma unroll
                for (int kx = 0; kx < 8; kx++){
                    float xvv = xv[kx];
                    acc0 = fmaf(xvv, swdc[0][ic][ky][kx], acc0);
                    acc1 = fmaf(xvv, swdc[1][ic][ky][kx], acc1);
                    acc2 = fmaf(xvv, swdc[2][ic][ky][kx], acc2);
                    acc3 = fmaf(xvv, swdc[3][ic][ky][kx], acc3);
                }
            }
        }
        acc0 += b_in[4*g+0]; acc1 += b_in[4*g+1]; acc2 += b_in[4*g+2]; acc3 += b_in[4*g+3];
        int p = ty*32 + tx;
        g_h[(b*MID + 4*g + 0)*P + p] = acc0;
        g_h[(b*MID + 4*g + 1)*P + p] = acc1;
        g_h[(b*MID + 4*g + 2)*P + p] = acc2;
        g_h[(b*MID + 4*g + 3)*P + p] = acc3;
        float s  = acc0 + acc1 + acc2 + acc3;
        float s2 = acc0*acc0 + acc1*acc1 + acc2*acc2 + acc3*acc3;
        #pragma unroll
        for (int o = 16; o; o >>= 1){
            s  += __shfl_xor_sync(0xffffffffu, s,  o);
            s2 += __shfl_xor_sync(0xffffffffu, s2, o);
        }
        int wid = tid >> 5, lid = tid & 31;
        if (lid == 0){ red[wid] = s; red[32+wid] = s2; }
        __syncthreads();
        if (tid < 32){
            s = red[tid]; s2 = red[32+tid];
            #pragma unroll
            for (int o = 16; o; o >>= 1){
                s  += __shfl_xor_sync(0xffffffffu, s,  o);
                s2 += __shfl_xor_sync(0xffffffffu, s2, o);
            }
            if (tid == 0){
                int grp = g >> 4;
                g_gnp0[(b*2 + grp)*16 + (g & 15)] = make_float2(s, s2);
            }
        }
    }
    grid_bar_b(b);

    // ================= mamba blocks =================
    #pragma unroll 1
    for (int blk = 0; blk < 2; blk++){
        const float* w     = blk ? ip1w : ip0w;
        const float* cw    = blk ? c1w  : c0w;
        const float* cb    = blk ? c1b  : c0b;
        const float* gamma = blk ? gn1g : gn0g;
        const float* beta  = blk ? gn1b : gn0b;
        const float* xproj = blk ? xp1  : xp0;
        const float* dtw   = blk ? dt1w : dt0w;
        const float* dtb   = blk ? dt1b : dt0b;
        const float* alog  = blk ? al1  : al0;
        const float* dd    = blk ? dd1  : dd0;

        // ---------- inproj: GN + 3x3 conv + conv0+SiLU + gate + x_dbl ----------
        {
            int g = q;
            int p = tid;
            int wq = p >> 5, lane = p & 31;
            int cx0 = 2*g, cx1 = 2*g+1, cg0 = 64+2*g, cg1 = 65+2*g;
            // prefetch residual loads (independent of stats)
            float hv0 = g_h[(b*MID + cx0)*P + p];
            float hv1 = g_h[(b*MID + cx1)*P + p];
            float hv2 = g_h[(b*MID + cg0)*P + p];
            float hv3 = g_h[(b*MID + cg1)*P + p];
            if (wq < 2){
                int npart = blk ? 32 : 16;
                float2 v = make_float2(0.f, 0.f);
                if (lane < npart) v = blk ? g_gnp1[(b*2+wq)*32 + lane] : g_gnp0[(b*2+wq)*16 + lane];
                float s = v.x, s2v = v.y;
                #pragma unroll
                for (int o = 16; o; o >>= 1){
                    s   += __shfl_xor_sync(0xffffffffu, s,   o);
                    s2v += __shfl_xor_sync(0xffffffffu, s2v, o);
                }
                if (lane == 0){
                    float mean = s * (1.f/65536.f);
                    float var  = s2v * (1.f/65536.f) - mean*mean;
                    sMI[wq*2]   = mean;
                    sMI[wq*2+1] = rsqrtf(var + 1e-5f);
                }
            }
            if (p >= 64 && p < 100){
                int idx = p - 64;
                int t = idx / 4, j = idx & 3;
                float4 wv;
                wv.x = w[(4*g + j)*18 +     t];
                wv.y = w[(4*g + j)*18 + 9 + t];
                wv.z = w[(128 + 4*g + j)*18 +     t];
                wv.w = w[(128 + 4*g + j)*18 + 9 + t];
                sW4[t][j] = wv;
            }
            if (p >= 128 && p < 260){
                int i = p - 128;
                int cell;
                if (i < 34)       cell = i;
                else if (i < 68)  cell = 33*34 + (i - 34);
                else if (i < 100) cell = (i - 68 + 1)*34;
                else              cell = (i - 100 + 1)*34 + 33;
                sP[cell] = make_float4(0.f, 0.f, 0.f, 0.f);
            }
            __syncthreads();
            int y = p >> 5, xx0 = p & 31;
            {
                float m0 = sMI[0], i0 = sMI[1], m1 = sMI[2], i1 = sMI[3];
                float ga0 = gamma[cx0]*i0, be0 = beta[cx0] - m0*ga0;
                float ga1 = gamma[cx1]*i0, be1 = beta[cx1] - m0*ga1;
                float ga2 = gamma[cg0]*i1, be2 = beta[cg0] - m1*ga2;
                float ga3 = gamma[cg1]*i1, be3 = beta[cg1] - m1*ga3;
                float4 v;
                v.x = hv0*ga0 + be0;
                v.y = hv1*ga1 + be1;
                v.z = hv2*ga2 + be2;
                v.w = hv3*ga3 + be3;
                sP[(y+1)*34 + (xx0+1)] = v;
            }
            __syncthreads();
            float accx[4] = {0.f,0.f,0.f,0.f};
            float accg[4] = {0.f,0.f,0.f,0.f};
            #pragma unroll
            for (int ky = 0; ky < 3; ky++){
                #pragma unroll
                for (int kx = 0; kx < 3; kx++){
                    float4 v = sP[(y+ky)*34 + (xx0+kx)];
                    int t = ky*3 + kx;
                    #pragma unroll
                    for (int j = 0; j < 4; j++){
                        float4 W = sW4[t][j];
                        accx[j] = fmaf(v.x, W.x, fmaf(v.y, W.y, accx[j]));
                        accg[j] = fmaf(v.z, W.z, fmaf(v.w, W.w, accg[j]));
                    }
                }
            }
            #pragma unroll
            for (int j = 0; j < 4; j++){
                int c = 4*g + j;
                g_res[(b*MID + c)*P + p] = silu_f(accg[j]);
            }
            #pragma unroll
            for (int j = 0; j < 4; j++){
                int c = 4*g + j;
                float lo = (j < 2) ? accx[0] : accx[2];
                float hi = (j < 2) ? accx[1] : accx[3];
                float v = fmaf(lo, cw[c*2], fmaf(hi, cw[c*2+1], cb[c]));
                float uv = silu_f(v);
                g_u[(b*MID + c)*P + p] = uv;
                sU[j][p] = uv;
            }
            __syncthreads();
            // x_dbl rows 4g..4g+3: warp wq handles k = 3wq..3wq+2, software-pipelined loads
            const float4* xpr0 = (const float4*)(xproj + (wq*3 + 0)*P);
            const float4* xpr1 = (const float4*)(xproj + (wq*3 + 1)*P);
            const float4* xpr2 = (const float4*)(xproj + (wq*3 + 2)*P);
            const float4* u0p = (const float4*)sU[0];
            const float4* u1p = (const float4*)sU[1];
            const float4* u2p = (const float4*)sU[2];
            const float4* u3p = (const float4*)sU[3];
            float a00=0,a01=0,a02=0, a10=0,a11=0,a12=0, a20=0,a21=0,a22=0, a30=0,a31=0,a32=0;
            float4 w0n = xpr0[lane], w1n = xpr1[lane], w2n = xpr2[lane];
            #pragma unroll
            for (int i = 0; i < 8; i++){
                int px = i*32 + lane;
                float4 w0 = w0n, w1 = w1n, w2 = w2n;
                if (i < 7){
                    int pxn = px + 32;
                    w0n = xpr0[pxn]; w1n = xpr1[pxn]; w2n = xpr2[pxn];
                }
                float4 u0 = u0p[px], u1 = u1p[px], u2 = u2p[px], u3 = u3p[px];
                a00 = fmaf(u0.x,w0.x,a00); a00 = fmaf(u0.y,w0.y,a00); a00 = fmaf(u0.z,w0.z,a00); a00 = fmaf(u0.w,w0.w,a00);
                a01 = fmaf(u0.x,w1.x,a01); a01 = fmaf(u0.y,w1.y,a01); a01 = fmaf(u0.z,w1.z,a01); a01 = fmaf(u0.w,w1.w,a01);
                a02 = fmaf(u0.x,w2.x,a02); a02 = fmaf(u0.y,w2.y,a02); a02 = fmaf(u0.z,w2.z,a02); a02 = fmaf(u0.w,w2.w,a02);
                a10 = fmaf(u1.x,w0.x,a10); a10 = fmaf(u1.y,w0.y,a10); a10 = fmaf(u1.z,w0.z,a10); a10 = fmaf(u1.w,w0.w,a10);
                a11 = fmaf(u1.x,w1.x,a11); a11 = fmaf(u1.y,w1.y,a11); a11 = fmaf(u1.z,w1.z,a11); a11 = fmaf(u1.w,w1.w,a11);
                a12 = fmaf(u1.x,w2.x,a12); a12 = fmaf(u1.y,w2.y,a12); a12 = fmaf(u1.z,w2.z,a12); a12 = fmaf(u1.w,w2.w,a12);
                a20 = fmaf(u2.x,w0.x,a20); a20 = fmaf(u2.y,w0.y,a20); a20 = fmaf(u2.z,w0.z,a20); a20 = fmaf(u2.w,w0.w,a20);
                a21 = fmaf(u2.x,w1.x,a21); a21 = fmaf(u2.y,w1.y,a21); a21 = fmaf(u2.z,w1.z,a21); a21 = fmaf(u2.w,w1.w,a21);
                a22 = fmaf(u2.x,w2.x,a22); a22 = fmaf(u2.y,w2.y,a22); a22 = fmaf(u2.z,w2.z,a22); a22 = fmaf(u2.w,w2.w,a22);
                a30 = fmaf(u3.x,w0.x,a30); a30 = fmaf(u3.y,w0.y,a30); a30 = fmaf(u3.z,w0.z,a30); a30 = fmaf(u3.w,w0.w,a30);
                a31 = fmaf(u3.x,w1.x,a31); a31 = fmaf(u3.y,w1.y,a31); a31 = fmaf(u3.z,w1.z,a31); a31 = fmaf(u3.w,w1.w,a31);
                a32 = fmaf(u3.x,w2.x,a32); a32 = fmaf(u3.y,w2.y,a32); a32 = fmaf(u3.z,w2.z,a32); a32 = fmaf(u3.w,w2.w,a32);
            }
            #pragma unroll
            for (int o = 16; o; o >>= 1){
                a00 += __shfl_xor_sync(0xffffffffu, a00, o); a01 += __shfl_xor_sync(0xffffffffu, a01, o);
                a02 += __shfl_xor_sync(0xffffffffu, a02, o); a10 += __shfl_xor_sync(0xffffffffu, a10, o);
                a11 += __shfl_xor_sync(0xffffffffu, a11, o); a12 += __shfl_xor_sync(0xffffffffu, a12, o);
                a20 += __shfl_xor_sync(0xffffffffu, a20, o); a21 += __shfl_xor_sync(0xffffffffu, a21, o);
                a22 += __shfl_xor_sync(0xffffffffu, a22, o); a30 += __shfl_xor_sync(0xffffffffu, a30, o);
                a31 += __shfl_xor_sync(0xffffffffu, a31, o); a32 += __shfl_xor_sync(0xffffffffu, a32, o);
            }
            if (lane == 0){
                int k = wq*3;
                float* r0 = g_xdbl + (b*LSEQ + 4*g + 0)*KDIM + k;
                float* r1 = g_xdbl + (b*LSEQ + 4*g + 1)*KDIM + k;
                float* r2 = g_xdbl + (b*LSEQ + 4*g + 2)*KDIM + k;
                float* r3 = g_xdbl + (b*LSEQ + 4*g + 3)*KDIM + k;
                r0[0]=a00; r0[1]=a01; r0[2]=a02;
                r1[0]=a10; r1[1]=a11; r1[2]=a12;
                r2[0]=a20; r2[1]=a21; r2[2]=a22;
                r3[0]=a30; r3[1]=a31; r3[2]=a32;
            }
        }
        grid_bar_b(b);

        // ---------- scan: delta GEMM + softplus + selective scan + combine + GN1 ----------
        {
            int dt = q;
            float*  sXd = sm;                    // [128][68]; later sY overlay
            float*  sWs = sm + 8704;             // [64][33]; later GN scratch
            float*  sB  = sm + 10816;            // [128][16]
            float*  sC  = sm + 12864;            // [128][16]
            float*  sDelta = sm + 14912;         // [128][33]
            float*  sUt    = sm + 19136;         // [128][33]
            float*  sY     = sm;                 // overlay

            for (int idx = tid; idx < 128*64; idx += 1024){
                int l = idx >> 6, k = idx & 63;
                sXd[l*68 + k] = g_xdbl[(b*LSEQ + l)*KDIM + k];
            }
            for (int idx = tid; idx < 128*16; idx += 1024){
                int l = idx >> 4, n = idx & 15;
                const float* row = g_xdbl + (b*LSEQ + l)*KDIM;
                sB[l*16 + n] = row[64 + n];
                sC[l*16 + n] = row[80 + n];
            }
            for (int idx = tid; idx < 32*64; idx += 1024){
                int dl = idx >> 6, r = idx & 63;
                sWs[r*33 + dl] = dtw[(dt*32 + dl)*64 + r];
            }
            for (int idx = tid; idx < 128*32; idx += 1024){
                int l = idx >> 5, dj = idx & 31;
                sUt[l*33 + dj] = g_u[(b*LSEQ + l)*P + dt*32 + dj];
            }
            __syncthreads();

            // delta GEMM: thread = (4 l's) x (dloc), pipelined weight loads
            {
                int dloc = tid & 31, lbase = (tid >> 5) << 2;
                float acc[4] = {0.f,0.f,0.f,0.f};
                float wv[16], wvn[16];
                #pragma unroll
                for (int j = 0; j < 16; j++) wvn[j] = sWs[j*33 + dloc];
                #pragma unroll
                for (int k0 = 0; k0 < 64; k0 += 16){
                    #pragma unroll
                    for (int j = 0; j < 16; j++) wv[j] = wvn[j];
                    if (k0 < 48){
                        #pragma unroll
                        for (int j = 0; j < 16; j++) wvn[j] = sWs[(k0+16+j)*33 + dloc];
                    }
                    #pragma unroll
                    for (int l = 0; l < 4; l++){
                        const float4* row = (const float4*)(sXd + (lbase+l)*68 + k0);
                        float4 x0 = row[0], x1 = row[1], x2 = row[2], x3 = row[3];
                        float a = acc[l];
                        a = fmaf(x0.x,wv[0],a);  a = fmaf(x0.y,wv[1],a);  a = fmaf(x0.z,wv[2],a);  a = fmaf(x0.w,wv[3],a);
                        a = fmaf(x1.x,wv[4],a);  a = fmaf(x1.y,wv[5],a);  a = fmaf(x1.z,wv[6],a);  a = fmaf(x1.w,wv[7],a);
                        a = fmaf(x2.x,wv[8],a);  a = fmaf(x2.y,wv[9],a);  a = fmaf(x2.z,wv[10],a); a = fmaf(x2.w,wv[11],a);
                        a = fmaf(x3.x,wv[12],a); a = fmaf(x3.y,wv[13],a); a = fmaf(x3.z,wv[14],a); a = fmaf(x3.w,wv[15],a);
                        acc[l] = a;
                    }
                }
                float bias = dtb[dt*32 + dloc];
                #pragma unroll
                for (int l = 0; l < 4; l++){
                    float xv = acc[l] + bias;
                    sDelta[(lbase+l)*33 + dloc] = fmaxf(xv, 0.f) + __logf(1.f + __expf(-fabsf(xv)));
                }
            }
            __syncthreads();

            // scan: 128 threads, thread = (dl = tid>>2) x (n-quad = (tid&3)*4), prefetched
            if (tid < 128){
                int dl = tid >> 2;
                int nq = (tid & 3) * 4;
                int d = dt*32 + dl;
                float An0 = -expf(alog[d*16 + nq + 0]);
                float An1 = -expf(alog[d*16 + nq + 1]);
                float An2 = -expf(alog[d*16 + nq + 2]);
                float An3 = -expf(alog[d*16 + nq + 3]);
                float Dd = dd[d];
                float cr0 = 0.f, cr1 = 0.f, cr2 = 0.f, cr3 = 0.f;
                float td_n = sDelta[dl];
                float tu_n = sUt[dl];
                float4 B4n = *(const float4*)&sB[nq];
                float4 C4n = *(const float4*)&sC[nq];
                #pragma unroll 4
                for (int l = 0; l < LSEQ; l++){
                    float td = td_n, tu = tu_n;
                    float4 B4 = B4n, C4 = C4n;
                    if (l < LSEQ-1){
                        td_n = sDelta[(l+1)*33 + dl];
                        tu_n = sUt[(l+1)*33 + dl];
                        B4n = *(const float4*)&sB[(l+1)*16 + nq];
                        C4n = *(const float4*)&sC[(l+1)*16 + nq];
                    }
                    float du = td * tu;
                    cr0 = fmaf(__expf(td*An0), cr0, du*B4.x);
                    cr1 = fmaf(__expf(td*An1), cr1, du*B4.y);
                    cr2 = fmaf(__expf(td*An2), cr2, du*B4.z);
                    cr3 = fmaf(__expf(td*An3), cr3, du*B4.w);
                    float yv = fmaf(cr0, C4.x, fmaf(cr1, C4.y, fmaf(cr2, C4.z, cr3*C4.w)));
                    yv += __shfl_xor_sync(0xffffffffu, yv, 1);
                    yv += __shfl_xor_sync(0xffffffffu, yv, 2);
                    if ((tid & 3) == 0) sY[l*33 + dl] = fmaf(tu, Dd, yv);
                }
            }
            __syncthreads();

            // combine h += y*silu(res) and GN1 partial stats
            float s0 = 0.f, q0 = 0.f, s1 = 0.f, q1 = 0.f;
            for (int e = tid; e < 128*32; e += 1024){
                int l = e >> 5, dj = e & 31;
                int idx = (b*LSEQ + l)*P + dt*32 + dj;
                float h = fmaf(sY[l*33 + dj], g_res[idx], g_h[idx]);
                g_h[idx] = h;
                if (l < 64){ s0 += h; q0 += h*h; } else { s1 += h; q1 += h*h; }
            }
            if (blk == 0){
                #pragma unroll
                for (int o = 16; o; o >>= 1){
                    s0 += __shfl_xor_sync(0xffffffffu, s0, o);
                    q0 += __shfl_xor_sync(0xffffffffu, q0, o);
                    s1 += __shfl_xor_sync(0xffffffffu, s1, o);
                    q1 += __shfl_xor_sync(0xffffffffu, q1, o);
                }
                int wid = tid >> 5;
                __syncthreads();
                if ((tid & 31) == 0){
                    sWs[wid*4+0] = s0; sWs[wid*4+1] = q0; sWs[wid*4+2] = s1; sWs[wid*4+3] = q1;
                }
                __syncthreads();
                if (tid == 0){
                    float S0=0,Q0=0,S1=0,Q1=0;
                    #pragma unroll
                    for (int i = 0; i < 32; i++){ S0+=sWs[i*4]; Q0+=sWs[i*4+1]; S1+=sWs[i*4+2]; Q1+=sWs[i*4+3]; }
                    g_gnp1[(b*2 + 0)*32 + dt] = make_float2(S0, Q0);
                    g_gnp1[(b*2 + 1)*32 + dt] = make_float2(S1, Q1);
                }
            }
        }
        grid_bar_b(b);
    }

    // ================= conv_out + x8 bilinear upsample (4 planes per block) =================
    {
        int lane64 = tid & 63;
        int ry2 = tid >> 6;                 // 0..15
        int ii = lane64 >> 1;               // source col 0..31
        int jh = lane64 & 1;                // which half of the 8-wide output group
        int ca = jh ? ii : (ii > 0 ? ii - 1 : 0);
        int cbx = jh ? (ii < 31 ? ii + 1 : 31) : ii;
        float wxa = jh ? 0.0625f : 0.5625f;
        #pragma unroll 1
        for (int i = 0; i < 4; i++){
            int plane = bid*4 + i;
            int pb = plane >> 7, oc = plane & 127;
            int g = oc >> 2;
            const float* hb = g_h + (size_t)(pb*MID + 4*g)*P;
            if (tid < 256){
                float w0 = wout[oc*4], w1 = wout[oc*4+1], w2 = wout[oc*4+2], w3 = wout[oc*4+3];
                float bias = bout[oc];
                float4 a  = ((const float4*)hb)[tid];
                float4 c1 = ((const float4*)(hb+P))[tid];
                float4 c2 = ((const float4*)(hb+2*P))[tid];
                float4 c3 = ((const float4*)(hb+3*P))[tid];
                float4 r;
                r.x = bias + a.x*w0 + c1.x*w1 + c2.x*w2 + c3.x*w3;
                r.y = bias + a.y*w0 + c1.y*w1 + c2.y*w2 + c3.y*w3;
                r.z = bias + a.z*w0 + c1.z*w1 + c2.z*w2 + c3.z*w3;
                r.w = bias + a.w*w0 + c1.w*w1 + c2.w*w2 + c3.w*w3;
                ((float4*)sCo)[tid] = r;
            }
            __syncthreads();
            float* obase = out + ((size_t)(pb*MID + oc))*256*256;
            #pragma unroll 4
            for (int t = 0; t < 16; t++){
                int oy = t*16 + ry2;
                float sy = (oy + 0.5f) * 0.125f - 0.5f;
                int iy = (int)floorf(sy);
                float fy = sy - (float)iy;
                int iy0 = iy < 0 ? 0 : iy;
                int iy1 = (iy + 1 > 31) ? 31 : iy + 1;
                const float* r0 = sCo + iy0*32;
                const float* r1 = sCo + iy1*32;
                float a0 = r0[ca], a1 = r1[ca];
                float b0 = r0[cbx], b1 = r1[cbx];
                float va = a0 + (a1 - a0) * fy;
                float vb = b0 + (b1 - b0) * fy;
                float dab = vb - va;
                float4 v;
                v.x = fmaf(dab, wxa,            va);
                v.y = fmaf(dab, wxa + 0.125f,   va);
                v.z = fmaf(dab, wxa + 0.25f,    va);
                v.w = fmaf(dab, wxa + 0.375f,   va);
                ((float4*)(obase + oy*256))[lane64] = v;
            }
            __syncthreads();
        }
    }
}

// ---------------- host orchestration ----------------
extern "C" void kernel_launch(void* const* d_in, const int* in_sizes, int n_in,
                              void* d_out, int out_size){
    cudaFuncSetAttribute(k_mega, cudaFuncAttributeMaxDynamicSharedMemorySize, SCAN_SMEM_BYTES);

    k_mega<<<NBLK, 1024, SCAN_SMEM_BYTES>>>(
        (const float*)d_in[0],  (const float*)d_in[1],  (const float*)d_in[2],
        (const float*)d_in[3],  (const float*)d_in[4],  (const float*)d_in[5],
        (const float*)d_in[6],  (const float*)d_in[7],  (const float*)d_in[8],
        (const float*)d_in[9],  (const float*)d_in[10], (const float*)d_in[11],
        (const float*)d_in[12],
        (const float*)d_in[13], (const float*)d_in[14], (const float*)d_in[15],
        (const float*)d_in[16], (const float*)d_in[17], (const float*)d_in[18],
        (const float*)d_in[19], (const float*)d_in[20], (const float*)d_in[21],
        (const float*)d_in[22],
        (const float*)d_in[23], (const float*)d_in[24], (float*)d_out);
}